// round 8
// baseline (speedup 1.0000x reference)
#include <cuda_runtime.h>
#include <math_constants.h>

#define BB 8
#define NN 2048
#define KNN 20
#define NTOT (BB*NN)
#define EPSB 1e-5f
#define QB 32            // queries per knn block
#define SSUB 4           // subset scanners per query
#define SUBN (NN/SSUB)   // 512 points per subset

// ---------------- scratch (device globals; no allocation allowed) ----------
__device__ int      g_idx[NTOT*KNN];
__device__ float    g_x1[NTOT*64];
__device__ float    g_x2[NTOT*64];
__device__ float    g_x3[NTOT*64];
__device__ float    g_Y[NTOT*64];
__device__ float    g_T[NTOT*64];
__device__ float4   g_pts[NTOT];
__device__ unsigned g_gmax[BB*1024];

__device__ __forceinline__ float lrelu(float z){ return z >= 0.f ? z : 0.2f*z; }
__device__ __forceinline__ unsigned fenc(float f){
    unsigned u = __float_as_uint(f);
    return (u & 0x80000000u) ? ~u : (u | 0x80000000u);
}
__device__ __forceinline__ float fdec(unsigned e){
    return (e & 0x80000000u) ? __uint_as_float(e ^ 0x80000000u) : __uint_as_float(~e);
}

// ---------------- prep: pack knn source coords as float4 (x,y,z,|p|^2) -----
template<int SEL>
__global__ __launch_bounds__(256) void prep_pts_kernel(const float* __restrict__ x)
{
    int t = blockIdx.x*256 + threadIdx.x;
    if (t >= NTOT) return;
    const float* src = (SEL == 0) ? (x + (size_t)t*3)
                                  : (((SEL == 1) ? g_x1 : g_x2) + (size_t)t*64 + 6);
    float px = src[0], py = src[1], pz = src[2];
    g_pts[t] = make_float4(px, py, pz, px*px + py*py + pz*pz);
}

// ---------------- argmin over 20 registers, tree (ILP-friendly) ------------
__device__ __forceinline__ void argmin20(const float bd[KNN], float& thr, int& tp)
{
    float v[10]; int ix[10];
#pragma unroll
    for (int t = 0; t < 10; t++){
        bool c = bd[t] < bd[t+10];
        v[t]  = c ? bd[t] : bd[t+10];
        ix[t] = c ? t : t+10;
    }
#pragma unroll
    for (int t = 0; t < 5; t++){
        bool c = v[t] < v[t+5];
        v[t]  = c ? v[t] : v[t+5];
        ix[t] = c ? ix[t] : ix[t+5];
    }
    bool c01 = v[0] < v[1]; float a = c01 ? v[0] : v[1]; int ai = c01 ? ix[0] : ix[1];
    bool c23 = v[2] < v[3]; float b = c23 ? v[2] : v[3]; int bi = c23 ? ix[2] : ix[3];
    bool cab = a < b;       float m = cab ? a : b;       int mi = cab ? ai : bi;
    bool c4  = m < v[4];
    thr = c4 ? m : v[4];
    tp  = c4 ? mi : ix[4];
}

// ---------------- kNN v4: 4 subset-scanners per query + smem merge ---------
// grid (BB, NN/QB), 128 threads. thread = (ql = tid>>2 query, s = tid&3 subset)
__global__ __launch_bounds__(128) void knn_kernel()
{
    __shared__ float4 pts[NN];
    __shared__ float  sd[QB*83];
    __shared__ int    si[QB*83];

    int tid = threadIdx.x;
    int b = blockIdx.x;
    for (int j = tid; j < NN; j += 128)
        pts[j] = g_pts[(size_t)b*NN + j];
    __syncthreads();

    int ql = tid >> 2;
    int s  = tid & 3;
    int i  = blockIdx.y*QB + ql;
    float4 q = pts[i];

    int j0 = s*SUBN;
    float bd[KNN]; int bi[KNN];
#pragma unroll
    for (int t = 0; t < KNN; t++){
        float4 p = pts[j0 + t];
        bd[t] = 2.f*(q.x*p.x + q.y*p.y + q.z*p.z) - q.w - p.w;
        bi[t] = j0 + t;
    }
    float thr; int tp;
    argmin20(bd, thr, tp);

#pragma unroll 4
    for (int jj = KNN; jj < SUBN; jj++){
        float4 p = pts[j0 + jj];
        float nd = 2.f*(q.x*p.x + q.y*p.y + q.z*p.z) - q.w - p.w;
        if (nd > thr){
#pragma unroll
            for (int t = 0; t < KNN; t++)
                if (t == tp){ bd[t] = nd; bi[t] = j0 + jj; }
            argmin20(bd, thr, tp);
        }
    }

    // scanners 1..3 publish; scanner 0 keeps its list in registers
    if (s != 0){
        int base = ql*83 + s*21;
#pragma unroll
        for (int t = 0; t < KNN; t++){ sd[base + t] = bd[t]; si[base + t] = bi[t]; }
    }
    __syncthreads();

    if (s == 0){
#pragma unroll
        for (int ss = 1; ss < 4; ss++){
            int base = ql*83 + ss*21;
            for (int t = 0; t < KNN; t++){
                float nd = sd[base + t];
                if (nd > thr){
                    int nj = si[base + t];
#pragma unroll
                    for (int u = 0; u < KNN; u++)
                        if (u == tp){ bd[u] = nd; bi[u] = nj; }
                    argmin20(bd, thr, tp);
                }
            }
        }
        int* o = g_idx + ((size_t)b*NN + i)*KNN;
#pragma unroll
        for (int t = 0; t < KNN; t++) o[t] = bi[t];
    }
}

// ---------------- gemmYT v2: Y' = s*(x@Wlo^T), T' = s*(x@Wd^T)+b -----------
template<int C, int SEL>
__global__ __launch_bounds__(256) void gemmYT_kernel(
    const float* __restrict__ x, const float* __restrict__ W,
    const float* __restrict__ bng, const float* __restrict__ bnb,
    const float* __restrict__ bnm, const float* __restrict__ bnv)
{
    const float* __restrict__ xin = (SEL == 0) ? x : (SEL == 1) ? g_x1 : g_x2;

    __shared__ __align__(16) float Wlo[C*64];
    __shared__ __align__(16) float Wd [C*64];
    __shared__ __align__(16) float xS [32*C];

    int tid = threadIdx.x;
    int pt0 = blockIdx.x*32;

    for (int t = tid; t < C*64; t += 256){
        int o = t & 63, c = t >> 6;
        float lo = W[(size_t)o*(2*C) + c];
        Wlo[c*64 + o] = lo;
        Wd [c*64 + o] = W[(size_t)o*(2*C) + C + c] - lo;
    }
    for (int t = tid; t < 32*C; t += 256){
        int p = t / C, c = t % C;
        xS[p*C + c] = xin[((size_t)pt0 + p)*C + c];
    }
    __syncthreads();

    int o0 = (tid & 15)*4;
    int p0 = (tid >> 4)*2, p1 = p0 + 1;

    float aY0[4]={0,0,0,0}, aT0[4]={0,0,0,0};
    float aY1[4]={0,0,0,0}, aT1[4]={0,0,0,0};

#pragma unroll 4
    for (int c = 0; c < C; c++){
        float4 wl = *(const float4*)&Wlo[c*64 + o0];
        float4 wd = *(const float4*)&Wd [c*64 + o0];
        float x0 = xS[p0*C + c];
        float x1 = xS[p1*C + c];
        aY0[0]=fmaf(x0,wl.x,aY0[0]); aY0[1]=fmaf(x0,wl.y,aY0[1]);
        aY0[2]=fmaf(x0,wl.z,aY0[2]); aY0[3]=fmaf(x0,wl.w,aY0[3]);
        aT0[0]=fmaf(x0,wd.x,aT0[0]); aT0[1]=fmaf(x0,wd.y,aT0[1]);
        aT0[2]=fmaf(x0,wd.z,aT0[2]); aT0[3]=fmaf(x0,wd.w,aT0[3]);
        aY1[0]=fmaf(x1,wl.x,aY1[0]); aY1[1]=fmaf(x1,wl.y,aY1[1]);
        aY1[2]=fmaf(x1,wl.z,aY1[2]); aY1[3]=fmaf(x1,wl.w,aY1[3]);
        aT1[0]=fmaf(x1,wd.x,aT1[0]); aT1[1]=fmaf(x1,wd.y,aT1[1]);
        aT1[2]=fmaf(x1,wd.z,aT1[2]); aT1[3]=fmaf(x1,wd.w,aT1[3]);
    }

    float4 gv = *(const float4*)&bng[o0];
    float4 bv = *(const float4*)&bnb[o0];
    float4 mv = *(const float4*)&bnm[o0];
    float4 vv = *(const float4*)&bnv[o0];
    float s[4], bo[4];
    s[0] = gv.x*rsqrtf(vv.x + EPSB); bo[0] = bv.x - mv.x*s[0];
    s[1] = gv.y*rsqrtf(vv.y + EPSB); bo[1] = bv.y - mv.y*s[1];
    s[2] = gv.z*rsqrtf(vv.z + EPSB); bo[2] = bv.z - mv.z*s[2];
    s[3] = gv.w*rsqrtf(vv.w + EPSB); bo[3] = bv.w - mv.w*s[3];

    float4 r;
    r = make_float4(s[0]*aY0[0], s[1]*aY0[1], s[2]*aY0[2], s[3]*aY0[3]);
    *(float4*)&g_Y[((size_t)pt0 + p0)*64 + o0] = r;
    r = make_float4(s[0]*aY1[0], s[1]*aY1[1], s[2]*aY1[2], s[3]*aY1[3]);
    *(float4*)&g_Y[((size_t)pt0 + p1)*64 + o0] = r;
    r = make_float4(fmaf(s[0],aT0[0],bo[0]), fmaf(s[1],aT0[1],bo[1]),
                    fmaf(s[2],aT0[2],bo[2]), fmaf(s[3],aT0[3],bo[3]));
    *(float4*)&g_T[((size_t)pt0 + p0)*64 + o0] = r;
    r = make_float4(fmaf(s[0],aT1[0],bo[0]), fmaf(s[1],aT1[1],bo[1]),
                    fmaf(s[2],aT1[2],bo[2]), fmaf(s[3],aT1[3],bo[3]));
    *(float4*)&g_T[((size_t)pt0 + p1)*64 + o0] = r;
}

// ---------------- edge_conv2: h1=lrelu(Y'[j]+T'[i]) tile -> conv-b -> k-max -
template<int SEL_OUT>
__global__ __launch_bounds__(512) void edge_conv2_kernel(
    const float* __restrict__ Wb,
    const float* __restrict__ bng, const float* __restrict__ bnb,
    const float* __restrict__ bnm, const float* __restrict__ bnv)
{
    float* __restrict__ xout = (SEL_OUT == 1) ? g_x1 : g_x2;

    __shared__ __align__(16) float Ws[64*64];
    __shared__ __align__(16) float As[64*161];
    __shared__ __align__(16) float red[4*8*64];
    __shared__ int idxS[160];

    int tid = threadIdx.x;
    int pt0 = blockIdx.x*8;

    for (int t = tid; t < 4096; t += 512){
        int o = t & 63, c = t >> 6;
        Ws[c*64 + o] = Wb[(size_t)o*64 + c];
    }
    if (tid < 160) idxS[tid] = g_idx[(size_t)pt0*KNN + tid];
    __syncthreads();

    for (int e = tid; e < 160*64; e += 512){
        int r = e >> 6, c = e & 63;
        int p = r / KNN;
        int bb = (pt0 + p) >> 11;
        int j = idxS[r];
        float v = g_Y[((size_t)bb*NN + j)*64 + c] + g_T[((size_t)pt0 + p)*64 + c];
        As[c*161 + r] = lrelu(v);
    }

    int r5 = tid & 31;
    int tn = tid >> 5;
    int o0 = tn*4;

    float s2[4], b2[4];
#pragma unroll
    for (int q = 0; q < 4; q++){
        int o = o0 + q;
        float r = rsqrtf(bnv[o] + EPSB);
        s2[q] = bng[o]*r; b2[q] = bnb[o] - bnm[o]*s2[q];
    }
    __syncthreads();

    float acc[5][4];
#pragma unroll
    for (int i = 0; i < 5; i++)
#pragma unroll
        for (int q = 0; q < 4; q++) acc[i][q] = 0.f;

#pragma unroll 4
    for (int c = 0; c < 64; c++){
        float4 w = *(const float4*)&Ws[c*64 + o0];
        float a0 = As[c*161 + r5*5 + 0];
        float a1 = As[c*161 + r5*5 + 1];
        float a2 = As[c*161 + r5*5 + 2];
        float a3 = As[c*161 + r5*5 + 3];
        float a4 = As[c*161 + r5*5 + 4];
        acc[0][0]=fmaf(a0,w.x,acc[0][0]); acc[0][1]=fmaf(a0,w.y,acc[0][1]);
        acc[0][2]=fmaf(a0,w.z,acc[0][2]); acc[0][3]=fmaf(a0,w.w,acc[0][3]);
        acc[1][0]=fmaf(a1,w.x,acc[1][0]); acc[1][1]=fmaf(a1,w.y,acc[1][1]);
        acc[1][2]=fmaf(a1,w.z,acc[1][2]); acc[1][3]=fmaf(a1,w.w,acc[1][3]);
        acc[2][0]=fmaf(a2,w.x,acc[2][0]); acc[2][1]=fmaf(a2,w.y,acc[2][1]);
        acc[2][2]=fmaf(a2,w.z,acc[2][2]); acc[2][3]=fmaf(a2,w.w,acc[2][3]);
        acc[3][0]=fmaf(a3,w.x,acc[3][0]); acc[3][1]=fmaf(a3,w.y,acc[3][1]);
        acc[3][2]=fmaf(a3,w.z,acc[3][2]); acc[3][3]=fmaf(a3,w.w,acc[3][3]);
        acc[4][0]=fmaf(a4,w.x,acc[4][0]); acc[4][1]=fmaf(a4,w.y,acc[4][1]);
        acc[4][2]=fmaf(a4,w.z,acc[4][2]); acc[4][3]=fmaf(a4,w.w,acc[4][3]);
    }

    int p    = r5 >> 2;
    int part = r5 & 3;
#pragma unroll
    for (int q = 0; q < 4; q++){
        float mx = -CUDART_INF_F;
#pragma unroll
        for (int i = 0; i < 5; i++)
            mx = fmaxf(mx, lrelu(fmaf(acc[i][q], s2[q], b2[q])));
        red[(part*8 + p)*64 + o0 + q] = mx;
    }
    __syncthreads();

    {
        int pp = tid >> 6, oo = tid & 63;
        float m = red[(0*8 + pp)*64 + oo];
        m = fmaxf(m, red[(1*8 + pp)*64 + oo]);
        m = fmaxf(m, red[(2*8 + pp)*64 + oo]);
        m = fmaxf(m, red[(3*8 + pp)*64 + oo]);
        xout[((size_t)pt0 + pp)*64 + oo] = m;
    }
}

// ---------------- edge_max (stage 3): x3 = max_k lrelu(Y'[j]+T'[i]) --------
__global__ __launch_bounds__(256) void edge_max_kernel()
{
    __shared__ int idxS[4*KNN];
    int tid = threadIdx.x;
    int pt0 = blockIdx.x*4;
    if (tid < 4*KNN) idxS[tid] = g_idx[(size_t)pt0*KNN + tid];
    __syncthreads();

    int p = tid >> 6, o = tid & 63;
    int pt = pt0 + p;
    int bb = pt >> 11;
    float tv = g_T[(size_t)pt*64 + o];
    float m = -CUDART_INF_F;
#pragma unroll
    for (int k = 0; k < KNN; k++){
        int j = idxS[p*KNN + k];
        m = fmaxf(m, lrelu(g_Y[((size_t)bb*NN + j)*64 + o] + tv));
    }
    g_x3[(size_t)pt*64 + o] = m;
}

// ---------------- init / final GEMM v2 / outputs ---------------------------
__global__ void init_gmax_kernel(){
    int t = blockIdx.x*256 + threadIdx.x;
    if (t < BB*1024) g_gmax[t] = 0u;
}

__global__ __launch_bounds__(256) void final_kernel(
    const float* __restrict__ W6,
    const float* __restrict__ bn6g, const float* __restrict__ bn6b,
    const float* __restrict__ bn6m, const float* __restrict__ bn6v)
{
    extern __shared__ float dsm[];
    float* Bs = dsm;              // [192*68]
    float* As = dsm + 192*68;     // [192*68]
    __shared__ float ss6[64], sb6[64];
    __shared__ float red[64*16];

    int tid = threadIdx.x;
    int n0 = blockIdx.x*64;
    int bb = blockIdx.y;
    int mc = blockIdx.z;

    if (tid < 64){
        int o = n0 + tid;
        float r = rsqrtf(bn6v[o] + EPSB);
        ss6[tid] = bn6g[o]*r; sb6[tid] = bn6b[o] - bn6m[o]*ss6[tid];
    }

    for (int ch = 0; ch < 3; ch++)
        for (int t = tid; t < 4096; t += 256){
            int nn = t >> 6, c = t & 63;
            Bs[(ch*64 + c)*68 + nn] = W6[(size_t)(n0+nn)*192 + ch*64 + c];
        }
    __syncthreads();

    int tm = tid & 15, tn = tid >> 4;
    float s6[4], b6[4];
#pragma unroll
    for (int q = 0; q < 4; q++){ s6[q] = ss6[tn*4+q]; b6[q] = sb6[tn*4+q]; }

    float vmax[4] = {-CUDART_INF_F, -CUDART_INF_F, -CUDART_INF_F, -CUDART_INF_F};

    for (int mi = mc*8; mi < mc*8 + 8; mi++){
        size_t m1 = (size_t)bb*NN + mi*64;
        __syncthreads();
        {
            for (int t = tid; t < 4096; t += 256){
                int m = t >> 6, c = t & 63;
                As[(0*64 + c)*68 + m] = g_x1[(m1 + m)*64 + c];
            }
            for (int t = tid; t < 4096; t += 256){
                int m = t >> 6, c = t & 63;
                As[(1*64 + c)*68 + m] = g_x2[(m1 + m)*64 + c];
            }
            for (int t = tid; t < 4096; t += 256){
                int m = t >> 6, c = t & 63;
                As[(2*64 + c)*68 + m] = g_x3[(m1 + m)*64 + c];
            }
        }
        __syncthreads();

        float acc[4][4];
#pragma unroll
        for (int i = 0; i < 4; i++)
#pragma unroll
            for (int j = 0; j < 4; j++) acc[i][j] = 0.f;

#pragma unroll 8
        for (int c = 0; c < 192; c++){
            float4 a  = *(const float4*)&As[c*68 + tm*4];
            float4 bv = *(const float4*)&Bs[c*68 + tn*4];
            acc[0][0] = fmaf(a.x,bv.x,acc[0][0]); acc[0][1] = fmaf(a.x,bv.y,acc[0][1]);
            acc[0][2] = fmaf(a.x,bv.z,acc[0][2]); acc[0][3] = fmaf(a.x,bv.w,acc[0][3]);
            acc[1][0] = fmaf(a.y,bv.x,acc[1][0]); acc[1][1] = fmaf(a.y,bv.y,acc[1][1]);
            acc[1][2] = fmaf(a.y,bv.z,acc[1][2]); acc[1][3] = fmaf(a.y,bv.w,acc[1][3]);
            acc[2][0] = fmaf(a.z,bv.x,acc[2][0]); acc[2][1] = fmaf(a.z,bv.y,acc[2][1]);
            acc[2][2] = fmaf(a.z,bv.z,acc[2][2]); acc[2][3] = fmaf(a.z,bv.w,acc[2][3]);
            acc[3][0] = fmaf(a.w,bv.x,acc[3][0]); acc[3][1] = fmaf(a.w,bv.y,acc[3][1]);
            acc[3][2] = fmaf(a.w,bv.z,acc[3][2]); acc[3][3] = fmaf(a.w,bv.w,acc[3][3]);
        }
#pragma unroll
        for (int nq = 0; nq < 4; nq++)
#pragma unroll
            for (int mq = 0; mq < 4; mq++)
                vmax[nq] = fmaxf(vmax[nq], lrelu(fmaf(acc[mq][nq], s6[nq], b6[nq])));
    }

    __syncthreads();
#pragma unroll
    for (int nq = 0; nq < 4; nq++) red[(tn*4+nq)*16 + tm] = vmax[nq];
    __syncthreads();
    if (tid < 64){
        float mx = -CUDART_INF_F;
#pragma unroll
        for (int t = 0; t < 16; t++) mx = fmaxf(mx, red[tid*16 + t]);
        atomicMax(&g_gmax[bb*1024 + n0 + tid], fenc(mx));
    }
}

__global__ void feat_kernel(float* __restrict__ out){
    int t = blockIdx.x*256 + threadIdx.x;
    if (t < BB*1024) out[t] = fdec(g_gmax[t]);
}

// ---------------- x4^T via smem transpose ----------------------------------
__global__ __launch_bounds__(256) void x4t_kernel(float* __restrict__ out)
{
    __shared__ float T[64*65];
    int tid = threadIdx.x;
    int n0 = blockIdx.x*64;
    int bb = blockIdx.y;
    int ch = blockIdx.z;
    const float* src = (ch == 0) ? g_x1 : (ch == 1) ? g_x2 : g_x3;

    for (int t = tid; t < 4096; t += 256){
        int c = t & 63, n = t >> 6;
        T[c*65 + n] = src[((size_t)bb*NN + n0 + n)*64 + c];
    }
    __syncthreads();
    size_t base = (size_t)BB*1024 + (size_t)bb*192*NN + (size_t)ch*64*NN;
    for (int t = tid; t < 4096; t += 256){
        int n = t & 63, c = t >> 6;
        out[base + (size_t)c*NN + n0 + n] = T[c*65 + n];
    }
}

// ---------------- launch ----------------------------------------------------
extern "C" void kernel_launch(void* const* d_in, const int* in_sizes, int n_in,
                              void* d_out, int out_size)
{
    const float* x    = (const float*)d_in[0];
    const float* W1   = (const float*)d_in[1];
    const float* W2   = (const float*)d_in[2];
    const float* W3   = (const float*)d_in[3];
    const float* W4   = (const float*)d_in[4];
    const float* W5   = (const float*)d_in[5];
    const float* W6   = (const float*)d_in[6];
    const float* bng  = (const float*)d_in[7];
    const float* bnb  = (const float*)d_in[8];
    const float* bnm  = (const float*)d_in[9];
    const float* bnv  = (const float*)d_in[10];
    const float* bn6g = (const float*)d_in[11];
    const float* bn6b = (const float*)d_in[12];
    const float* bn6m = (const float*)d_in[13];
    const float* bn6v = (const float*)d_in[14];
    float* out = (float*)d_out;

    cudaFuncSetAttribute(final_kernel,
        cudaFuncAttributeMaxDynamicSharedMemorySize, 2*192*68*4);
    const int FSMEM = 2*192*68*4;

    // Stage 1                                                       (launch idx)
    prep_pts_kernel<0><<<NTOT/256, 256>>>(x);                                 // 0
    gemmYT_kernel<3,0><<<NTOT/32, 256>>>(x, W1, bng, bnb, bnm, bnv);          // 1
    init_gmax_kernel<<<32, 256>>>();                                          // 2
    knn_kernel<<<dim3(BB, NN/QB), 128>>>();                                   // 3  <- ncu capture
    edge_conv2_kernel<1><<<NTOT/8, 512>>>(W2, bng+64, bnb+64, bnm+64, bnv+64);// 4

    // Stage 2
    prep_pts_kernel<1><<<NTOT/256, 256>>>(x);                                 // 5
    knn_kernel<<<dim3(BB, NN/QB), 128>>>();                                   // 6
    gemmYT_kernel<64,1><<<NTOT/32, 256>>>(x, W3, bng+2*64, bnb+2*64, bnm+2*64, bnv+2*64); // 7
    edge_conv2_kernel<2><<<NTOT/8, 512>>>(W4, bng+3*64, bnb+3*64, bnm+3*64, bnv+3*64);    // 8

    // Stage 3
    prep_pts_kernel<2><<<NTOT/256, 256>>>(x);                                 // 9
    knn_kernel<<<dim3(BB, NN/QB), 128>>>();                                   // 10
    gemmYT_kernel<64,2><<<NTOT/32, 256>>>(x, W5, bng+4*64, bnb+4*64, bnm+4*64, bnv+4*64); // 11
    edge_max_kernel<<<NTOT/4, 256>>>();                                       // 12

    // Final block + global max pool
    final_kernel<<<dim3(1024/64, BB, 4), 256, FSMEM>>>(W6, bn6g, bn6b, bn6m, bn6v);
    feat_kernel<<<32, 256>>>(out);
    x4t_kernel<<<dim3(NN/64, BB, 3), 256>>>(out);
}

// round 9
// speedup vs baseline: 1.8773x; 1.8773x over previous
#include <cuda_runtime.h>
#include <math_constants.h>

#define BB 8
#define NN 2048
#define KNN 20
#define NTOT (BB*NN)
#define EPSB 1e-5f
#define FULLM 0xFFFFFFFFu

// ---------------- scratch (device globals; no allocation allowed) ----------
__device__ int      g_idx[NTOT*KNN];
__device__ float    g_x1[NTOT*64];
__device__ float    g_x2[NTOT*64];
__device__ float    g_x3[NTOT*64];
__device__ float    g_Y[NTOT*64];
__device__ float    g_T[NTOT*64];
__device__ float4   g_pts[NTOT];
__device__ unsigned g_gmax[BB*1024];

__device__ __forceinline__ float lrelu(float z){ return z >= 0.f ? z : 0.2f*z; }
__device__ __forceinline__ unsigned fenc(float f){
    unsigned u = __float_as_uint(f);
    return (u & 0x80000000u) ? ~u : (u | 0x80000000u);
}
__device__ __forceinline__ float fdec(unsigned e){
    return (e & 0x80000000u) ? __uint_as_float(e ^ 0x80000000u) : __uint_as_float(~e);
}

// ---------------- prep: pack knn source coords as float4 (x,y,z,|p|^2) -----
template<int SEL>
__global__ __launch_bounds__(256) void prep_pts_kernel(const float* __restrict__ x)
{
    int t = blockIdx.x*256 + threadIdx.x;
    if (t >= NTOT) return;
    const float* src = (SEL == 0) ? (x + (size_t)t*3)
                                  : (((SEL == 1) ? g_x1 : g_x2) + (size_t)t*64 + 6);
    float px = src[0], py = src[1], pz = src[2];
    g_pts[t] = make_float4(px, py, pz, px*px + py*py + pz*pz);
}

// ---------------- kNN v5: warp-per-query, warp-cooperative top-20 ----------
// grid (BB, NN/8), 256 thr = 8 warps = 8 queries/block.
// List distributed: lanes 0..19 hold one (bd,bi) each. Inserts are
// warp-uniform (ballot loop + butterfly argmin with (val,lane) tie-break).
__global__ __launch_bounds__(256) void knn_kernel()
{
    __shared__ float4 pts[NN];
    int tid = threadIdx.x;
    int b = blockIdx.x;
    for (int j = tid; j < NN; j += 256)
        pts[j] = g_pts[(size_t)b*NN + j];
    __syncthreads();

    int w = tid >> 5, lane = tid & 31;
    int i = blockIdx.y*8 + w;
    float4 q = pts[i];
    float qx2 = 2.f*q.x, qy2 = 2.f*q.y, qz2 = 2.f*q.z, qw = q.w;

    float bd = -CUDART_INF_F;   // valid for lane < 20
    int   bi = 0;
    float thr = -CUDART_INF_F;  // lower bound on current 20th-best

    for (int ch = 0; ch < NN/32; ch++){
        float4 p = pts[ch*32 + lane];
        float t = fmaf(qz2, p.z, -qw);
        t = fmaf(qy2, p.y, t);
        t = fmaf(qx2, p.x, t);
        float nd = t - p.w;
        unsigned mask = __ballot_sync(FULLM, nd > thr);
        while (mask){
            int src = __ffs(mask) - 1;
            mask &= mask - 1;
            float d = __shfl_sync(FULLM, nd, src);
            // butterfly argmin over list lanes (lex tie-break -> all agree)
            float mv = (lane < KNN) ? bd : CUDART_INF_F;
            int   ml = lane;
#pragma unroll
            for (int off = 16; off; off >>= 1){
                float ov = __shfl_xor_sync(FULLM, mv, off);
                int   ol = __shfl_xor_sync(FULLM, ml, off);
                bool take = (ov < mv) || (ov == mv && ol < ml);
                mv = take ? ov : mv;
                ml = take ? ol : ml;
            }
            if (d > mv && lane == ml){ bd = d; bi = ch*32 + src; }
            thr = mv;   // pre-insert min: safe lower bound for pruning
        }
    }
    if (lane < KNN)
        g_idx[((size_t)b*NN + i)*KNN + lane] = bi;
}

// ---------------- gemmYT v2: Y' = s*(x@Wlo^T), T' = s*(x@Wd^T)+b -----------
template<int C, int SEL>
__global__ __launch_bounds__(256) void gemmYT_kernel(
    const float* __restrict__ x, const float* __restrict__ W,
    const float* __restrict__ bng, const float* __restrict__ bnb,
    const float* __restrict__ bnm, const float* __restrict__ bnv)
{
    const float* __restrict__ xin = (SEL == 0) ? x : (SEL == 1) ? g_x1 : g_x2;

    __shared__ __align__(16) float Wlo[C*64];
    __shared__ __align__(16) float Wd [C*64];
    __shared__ __align__(16) float xS [32*C];

    int tid = threadIdx.x;
    int pt0 = blockIdx.x*32;

    for (int t = tid; t < C*64; t += 256){
        int o = t & 63, c = t >> 6;
        float lo = W[(size_t)o*(2*C) + c];
        Wlo[c*64 + o] = lo;
        Wd [c*64 + o] = W[(size_t)o*(2*C) + C + c] - lo;
    }
    for (int t = tid; t < 32*C; t += 256){
        int p = t / C, c = t % C;
        xS[p*C + c] = xin[((size_t)pt0 + p)*C + c];
    }
    __syncthreads();

    int o0 = (tid & 15)*4;
    int p0 = (tid >> 4)*2, p1 = p0 + 1;

    float aY0[4]={0,0,0,0}, aT0[4]={0,0,0,0};
    float aY1[4]={0,0,0,0}, aT1[4]={0,0,0,0};

#pragma unroll 4
    for (int c = 0; c < C; c++){
        float4 wl = *(const float4*)&Wlo[c*64 + o0];
        float4 wd = *(const float4*)&Wd [c*64 + o0];
        float x0 = xS[p0*C + c];
        float x1 = xS[p1*C + c];
        aY0[0]=fmaf(x0,wl.x,aY0[0]); aY0[1]=fmaf(x0,wl.y,aY0[1]);
        aY0[2]=fmaf(x0,wl.z,aY0[2]); aY0[3]=fmaf(x0,wl.w,aY0[3]);
        aT0[0]=fmaf(x0,wd.x,aT0[0]); aT0[1]=fmaf(x0,wd.y,aT0[1]);
        aT0[2]=fmaf(x0,wd.z,aT0[2]); aT0[3]=fmaf(x0,wd.w,aT0[3]);
        aY1[0]=fmaf(x1,wl.x,aY1[0]); aY1[1]=fmaf(x1,wl.y,aY1[1]);
        aY1[2]=fmaf(x1,wl.z,aY1[2]); aY1[3]=fmaf(x1,wl.w,aY1[3]);
        aT1[0]=fmaf(x1,wd.x,aT1[0]); aT1[1]=fmaf(x1,wd.y,aT1[1]);
        aT1[2]=fmaf(x1,wd.z,aT1[2]); aT1[3]=fmaf(x1,wd.w,aT1[3]);
    }

    float4 gv = *(const float4*)&bng[o0];
    float4 bv = *(const float4*)&bnb[o0];
    float4 mv = *(const float4*)&bnm[o0];
    float4 vv = *(const float4*)&bnv[o0];
    float s[4], bo[4];
    s[0] = gv.x*rsqrtf(vv.x + EPSB); bo[0] = bv.x - mv.x*s[0];
    s[1] = gv.y*rsqrtf(vv.y + EPSB); bo[1] = bv.y - mv.y*s[1];
    s[2] = gv.z*rsqrtf(vv.z + EPSB); bo[2] = bv.z - mv.z*s[2];
    s[3] = gv.w*rsqrtf(vv.w + EPSB); bo[3] = bv.w - mv.w*s[3];

    float4 r;
    r = make_float4(s[0]*aY0[0], s[1]*aY0[1], s[2]*aY0[2], s[3]*aY0[3]);
    *(float4*)&g_Y[((size_t)pt0 + p0)*64 + o0] = r;
    r = make_float4(s[0]*aY1[0], s[1]*aY1[1], s[2]*aY1[2], s[3]*aY1[3]);
    *(float4*)&g_Y[((size_t)pt0 + p1)*64 + o0] = r;
    r = make_float4(fmaf(s[0],aT0[0],bo[0]), fmaf(s[1],aT0[1],bo[1]),
                    fmaf(s[2],aT0[2],bo[2]), fmaf(s[3],aT0[3],bo[3]));
    *(float4*)&g_T[((size_t)pt0 + p0)*64 + o0] = r;
    r = make_float4(fmaf(s[0],aT1[0],bo[0]), fmaf(s[1],aT1[1],bo[1]),
                    fmaf(s[2],aT1[2],bo[2]), fmaf(s[3],aT1[3],bo[3]));
    *(float4*)&g_T[((size_t)pt0 + p1)*64 + o0] = r;
}

// ---------------- edge_conv2: h1=lrelu(Y'[j]+T'[i]) tile -> conv-b -> k-max -
template<int SEL_OUT>
__global__ __launch_bounds__(512) void edge_conv2_kernel(
    const float* __restrict__ Wb,
    const float* __restrict__ bng, const float* __restrict__ bnb,
    const float* __restrict__ bnm, const float* __restrict__ bnv)
{
    float* __restrict__ xout = (SEL_OUT == 1) ? g_x1 : g_x2;

    __shared__ __align__(16) float Ws[64*64];
    __shared__ __align__(16) float As[64*161];
    __shared__ __align__(16) float red[4*8*64];
    __shared__ int idxS[160];

    int tid = threadIdx.x;
    int pt0 = blockIdx.x*8;

    for (int t = tid; t < 4096; t += 512){
        int o = t & 63, c = t >> 6;
        Ws[c*64 + o] = Wb[(size_t)o*64 + c];
    }
    if (tid < 160) idxS[tid] = g_idx[(size_t)pt0*KNN + tid];
    __syncthreads();

    for (int e = tid; e < 160*64; e += 512){
        int r = e >> 6, c = e & 63;
        int p = r / KNN;
        int bb = (pt0 + p) >> 11;
        int j = idxS[r];
        float v = g_Y[((size_t)bb*NN + j)*64 + c] + g_T[((size_t)pt0 + p)*64 + c];
        As[c*161 + r] = lrelu(v);
    }

    int r5 = tid & 31;
    int tn = tid >> 5;
    int o0 = tn*4;

    float s2[4], b2[4];
#pragma unroll
    for (int q = 0; q < 4; q++){
        int o = o0 + q;
        float r = rsqrtf(bnv[o] + EPSB);
        s2[q] = bng[o]*r; b2[q] = bnb[o] - bnm[o]*s2[q];
    }
    __syncthreads();

    float acc[5][4];
#pragma unroll
    for (int i = 0; i < 5; i++)
#pragma unroll
        for (int q = 0; q < 4; q++) acc[i][q] = 0.f;

#pragma unroll 4
    for (int c = 0; c < 64; c++){
        float4 w = *(const float4*)&Ws[c*64 + o0];
        float a0 = As[c*161 + r5*5 + 0];
        float a1 = As[c*161 + r5*5 + 1];
        float a2 = As[c*161 + r5*5 + 2];
        float a3 = As[c*161 + r5*5 + 3];
        float a4 = As[c*161 + r5*5 + 4];
        acc[0][0]=fmaf(a0,w.x,acc[0][0]); acc[0][1]=fmaf(a0,w.y,acc[0][1]);
        acc[0][2]=fmaf(a0,w.z,acc[0][2]); acc[0][3]=fmaf(a0,w.w,acc[0][3]);
        acc[1][0]=fmaf(a1,w.x,acc[1][0]); acc[1][1]=fmaf(a1,w.y,acc[1][1]);
        acc[1][2]=fmaf(a1,w.z,acc[1][2]); acc[1][3]=fmaf(a1,w.w,acc[1][3]);
        acc[2][0]=fmaf(a2,w.x,acc[2][0]); acc[2][1]=fmaf(a2,w.y,acc[2][1]);
        acc[2][2]=fmaf(a2,w.z,acc[2][2]); acc[2][3]=fmaf(a2,w.w,acc[2][3]);
        acc[3][0]=fmaf(a3,w.x,acc[3][0]); acc[3][1]=fmaf(a3,w.y,acc[3][1]);
        acc[3][2]=fmaf(a3,w.z,acc[3][2]); acc[3][3]=fmaf(a3,w.w,acc[3][3]);
        acc[4][0]=fmaf(a4,w.x,acc[4][0]); acc[4][1]=fmaf(a4,w.y,acc[4][1]);
        acc[4][2]=fmaf(a4,w.z,acc[4][2]); acc[4][3]=fmaf(a4,w.w,acc[4][3]);
    }

    int p    = r5 >> 2;
    int part = r5 & 3;
#pragma unroll
    for (int q = 0; q < 4; q++){
        float mx = -CUDART_INF_F;
#pragma unroll
        for (int i = 0; i < 5; i++)
            mx = fmaxf(mx, lrelu(fmaf(acc[i][q], s2[q], b2[q])));
        red[(part*8 + p)*64 + o0 + q] = mx;
    }
    __syncthreads();

    {
        int pp = tid >> 6, oo = tid & 63;
        float m = red[(0*8 + pp)*64 + oo];
        m = fmaxf(m, red[(1*8 + pp)*64 + oo]);
        m = fmaxf(m, red[(2*8 + pp)*64 + oo]);
        m = fmaxf(m, red[(3*8 + pp)*64 + oo]);
        xout[((size_t)pt0 + pp)*64 + oo] = m;
    }
}

// ---------------- edge_max (stage 3): x3 = max_k lrelu(Y'[j]+T'[i]) --------
__global__ __launch_bounds__(256) void edge_max_kernel()
{
    __shared__ int idxS[4*KNN];
    int tid = threadIdx.x;
    int pt0 = blockIdx.x*4;
    if (tid < 4*KNN) idxS[tid] = g_idx[(size_t)pt0*KNN + tid];
    __syncthreads();

    int p = tid >> 6, o = tid & 63;
    int pt = pt0 + p;
    int bb = pt >> 11;
    float tv = g_T[(size_t)pt*64 + o];
    float m = -CUDART_INF_F;
#pragma unroll
    for (int k = 0; k < KNN; k++){
        int j = idxS[p*KNN + k];
        m = fmaxf(m, lrelu(g_Y[((size_t)bb*NN + j)*64 + o] + tv));
    }
    g_x3[(size_t)pt*64 + o] = m;
}

// ---------------- init / final GEMM v2 / outputs ---------------------------
__global__ void init_gmax_kernel(){
    int t = blockIdx.x*256 + threadIdx.x;
    if (t < BB*1024) g_gmax[t] = 0u;
}

__global__ __launch_bounds__(256) void final_kernel(
    const float* __restrict__ W6,
    const float* __restrict__ bn6g, const float* __restrict__ bn6b,
    const float* __restrict__ bn6m, const float* __restrict__ bn6v)
{
    extern __shared__ float dsm[];
    float* Bs = dsm;              // [192*68]
    float* As = dsm + 192*68;     // [192*68]
    __shared__ float ss6[64], sb6[64];
    __shared__ float red[64*16];

    int tid = threadIdx.x;
    int n0 = blockIdx.x*64;
    int bb = blockIdx.y;
    int mc = blockIdx.z;

    if (tid < 64){
        int o = n0 + tid;
        float r = rsqrtf(bn6v[o] + EPSB);
        ss6[tid] = bn6g[o]*r; sb6[tid] = bn6b[o] - bn6m[o]*ss6[tid];
    }

    for (int ch = 0; ch < 3; ch++)
        for (int t = tid; t < 4096; t += 256){
            int nn = t >> 6, c = t & 63;
            Bs[(ch*64 + c)*68 + nn] = W6[(size_t)(n0+nn)*192 + ch*64 + c];
        }
    __syncthreads();

    int tm = tid & 15, tn = tid >> 4;
    float s6[4], b6[4];
#pragma unroll
    for (int q = 0; q < 4; q++){ s6[q] = ss6[tn*4+q]; b6[q] = sb6[tn*4+q]; }

    float vmax[4] = {-CUDART_INF_F, -CUDART_INF_F, -CUDART_INF_F, -CUDART_INF_F};

    for (int mi = mc*8; mi < mc*8 + 8; mi++){
        size_t m1 = (size_t)bb*NN + mi*64;
        __syncthreads();
        {
            for (int t = tid; t < 4096; t += 256){
                int m = t >> 6, c = t & 63;
                As[(0*64 + c)*68 + m] = g_x1[(m1 + m)*64 + c];
            }
            for (int t = tid; t < 4096; t += 256){
                int m = t >> 6, c = t & 63;
                As[(1*64 + c)*68 + m] = g_x2[(m1 + m)*64 + c];
            }
            for (int t = tid; t < 4096; t += 256){
                int m = t >> 6, c = t & 63;
                As[(2*64 + c)*68 + m] = g_x3[(m1 + m)*64 + c];
            }
        }
        __syncthreads();

        float acc[4][4];
#pragma unroll
        for (int i = 0; i < 4; i++)
#pragma unroll
            for (int j = 0; j < 4; j++) acc[i][j] = 0.f;

#pragma unroll 8
        for (int c = 0; c < 192; c++){
            float4 a  = *(const float4*)&As[c*68 + tm*4];
            float4 bv = *(const float4*)&Bs[c*68 + tn*4];
            acc[0][0] = fmaf(a.x,bv.x,acc[0][0]); acc[0][1] = fmaf(a.x,bv.y,acc[0][1]);
            acc[0][2] = fmaf(a.x,bv.z,acc[0][2]); acc[0][3] = fmaf(a.x,bv.w,acc[0][3]);
            acc[1][0] = fmaf(a.y,bv.x,acc[1][0]); acc[1][1] = fmaf(a.y,bv.y,acc[1][1]);
            acc[1][2] = fmaf(a.y,bv.z,acc[1][2]); acc[1][3] = fmaf(a.y,bv.w,acc[1][3]);
            acc[2][0] = fmaf(a.z,bv.x,acc[2][0]); acc[2][1] = fmaf(a.z,bv.y,acc[2][1]);
            acc[2][2] = fmaf(a.z,bv.z,acc[2][2]); acc[2][3] = fmaf(a.z,bv.w,acc[2][3]);
            acc[3][0] = fmaf(a.w,bv.x,acc[3][0]); acc[3][1] = fmaf(a.w,bv.y,acc[3][1]);
            acc[3][2] = fmaf(a.w,bv.z,acc[3][2]); acc[3][3] = fmaf(a.w,bv.w,acc[3][3]);
        }
#pragma unroll
        for (int nq = 0; nq < 4; nq++)
#pragma unroll
            for (int mq = 0; mq < 4; mq++)
                vmax[nq] = fmaxf(vmax[nq], lrelu(fmaf(acc[mq][nq], s6[nq], b6[nq])));
    }

    __syncthreads();
#pragma unroll
    for (int nq = 0; nq < 4; nq++) red[(tn*4+nq)*16 + tm] = vmax[nq];
    __syncthreads();
    if (tid < 64){
        float mx = -CUDART_INF_F;
#pragma unroll
        for (int t = 0; t < 16; t++) mx = fmaxf(mx, red[tid*16 + t]);
        atomicMax(&g_gmax[bb*1024 + n0 + tid], fenc(mx));
    }
}

__global__ void feat_kernel(float* __restrict__ out){
    int t = blockIdx.x*256 + threadIdx.x;
    if (t < BB*1024) out[t] = fdec(g_gmax[t]);
}

// ---------------- x4^T via smem transpose ----------------------------------
__global__ __launch_bounds__(256) void x4t_kernel(float* __restrict__ out)
{
    __shared__ float T[64*65];
    int tid = threadIdx.x;
    int n0 = blockIdx.x*64;
    int bb = blockIdx.y;
    int ch = blockIdx.z;
    const float* src = (ch == 0) ? g_x1 : (ch == 1) ? g_x2 : g_x3;

    for (int t = tid; t < 4096; t += 256){
        int c = t & 63, n = t >> 6;
        T[c*65 + n] = src[((size_t)bb*NN + n0 + n)*64 + c];
    }
    __syncthreads();
    size_t base = (size_t)BB*1024 + (size_t)bb*192*NN + (size_t)ch*64*NN;
    for (int t = tid; t < 4096; t += 256){
        int n = t & 63, c = t >> 6;
        out[base + (size_t)c*NN + n0 + n] = T[c*65 + n];
    }
}

// ---------------- launch ----------------------------------------------------
extern "C" void kernel_launch(void* const* d_in, const int* in_sizes, int n_in,
                              void* d_out, int out_size)
{
    const float* x    = (const float*)d_in[0];
    const float* W1   = (const float*)d_in[1];
    const float* W2   = (const float*)d_in[2];
    const float* W3   = (const float*)d_in[3];
    const float* W4   = (const float*)d_in[4];
    const float* W5   = (const float*)d_in[5];
    const float* W6   = (const float*)d_in[6];
    const float* bng  = (const float*)d_in[7];
    const float* bnb  = (const float*)d_in[8];
    const float* bnm  = (const float*)d_in[9];
    const float* bnv  = (const float*)d_in[10];
    const float* bn6g = (const float*)d_in[11];
    const float* bn6b = (const float*)d_in[12];
    const float* bn6m = (const float*)d_in[13];
    const float* bn6v = (const float*)d_in[14];
    float* out = (float*)d_out;

    cudaFuncSetAttribute(final_kernel,
        cudaFuncAttributeMaxDynamicSharedMemorySize, 2*192*68*4);
    const int FSMEM = 2*192*68*4;

    // Stage 1                                                       (launch idx)
    prep_pts_kernel<0><<<NTOT/256, 256>>>(x);                                 // 0
    gemmYT_kernel<3,0><<<NTOT/32, 256>>>(x, W1, bng, bnb, bnm, bnv);          // 1
    init_gmax_kernel<<<32, 256>>>();                                          // 2
    knn_kernel<<<dim3(BB, NN/8), 256>>>();                                    // 3  <- ncu capture
    edge_conv2_kernel<1><<<NTOT/8, 512>>>(W2, bng+64, bnb+64, bnm+64, bnv+64);// 4

    // Stage 2
    prep_pts_kernel<1><<<NTOT/256, 256>>>(x);                                 // 5
    knn_kernel<<<dim3(BB, NN/8), 256>>>();                                    // 6
    gemmYT_kernel<64,1><<<NTOT/32, 256>>>(x, W3, bng+2*64, bnb+2*64, bnm+2*64, bnv+2*64); // 7
    edge_conv2_kernel<2><<<NTOT/8, 512>>>(W4, bng+3*64, bnb+3*64, bnm+3*64, bnv+3*64);    // 8

    // Stage 3
    prep_pts_kernel<2><<<NTOT/256, 256>>>(x);                                 // 9
    knn_kernel<<<dim3(BB, NN/8), 256>>>();                                    // 10
    gemmYT_kernel<64,2><<<NTOT/32, 256>>>(x, W5, bng+4*64, bnb+4*64, bnm+4*64, bnv+4*64); // 11
    edge_max_kernel<<<NTOT/4, 256>>>();                                       // 12

    // Final block + global max pool
    final_kernel<<<dim3(1024/64, BB, 4), 256, FSMEM>>>(W6, bn6g, bn6b, bn6m, bn6v);
    feat_kernel<<<32, 256>>>(out);
    x4t_kernel<<<dim3(NN/64, BB, 3), 256>>>(out);
}

// round 10
// speedup vs baseline: 2.3524x; 1.2531x over previous
#include <cuda_runtime.h>
#include <math_constants.h>

#define BB 8
#define NN 2048
#define KNN 20
#define NTOT (BB*NN)
#define EPSB 1e-5f
#define FULLM 0xFFFFFFFFu

// ---------------- scratch (device globals; no allocation allowed) ----------
__device__ int      g_idx[NTOT*KNN];
__device__ float    g_x1[NTOT*64];
__device__ float    g_x2[NTOT*64];
__device__ float    g_x3[NTOT*64];
__device__ float    g_Y[NTOT*64];
__device__ float    g_T[NTOT*64];
__device__ float4   g_pts[NTOT];
__device__ unsigned g_gmax[BB*1024];

__device__ __forceinline__ float lrelu(float z){ return z >= 0.f ? z : 0.2f*z; }
__device__ __forceinline__ unsigned fenc(float f){
    unsigned u = __float_as_uint(f);
    return (u & 0x80000000u) ? ~u : (u | 0x80000000u);
}
__device__ __forceinline__ float fdec(unsigned e){
    return (e & 0x80000000u) ? __uint_as_float(e ^ 0x80000000u) : __uint_as_float(~e);
}

// ---------------- prep: pack knn source coords as float4 (x,y,z,|p|^2) -----
template<int SEL>
__global__ __launch_bounds__(256) void prep_pts_kernel(const float* __restrict__ x)
{
    int t = blockIdx.x*256 + threadIdx.x;
    if (t >= NTOT) return;
    const float* src = (SEL == 0) ? (x + (size_t)t*3)
                                  : (((SEL == 1) ? g_x1 : g_x2) + (size_t)t*64 + 6);
    float px = src[0], py = src[1], pz = src[2];
    g_pts[t] = make_float4(px, py, pz, px*px + py*py + pz*pz);
}

// ---------------- kNN v6: warp-per-query, fmin-reduce inserts --------------
// grid (BB, NN/8), 256 thr = 8 warps = 8 queries/block. Lanes 0..19 hold the
// unsorted top-20. Insert: min-value butterfly (shfl+FMNMX) + ballot owner.
__device__ __forceinline__ void warp_insert(
    float d, int j, int lane, float& bd, int& bi, float& thr)
{
    float mv = (lane < KNN) ? bd : CUDART_INF_F;
#pragma unroll
    for (int off = 16; off; off >>= 1)
        mv = fminf(mv, __shfl_xor_sync(FULLM, mv, off));
    if (d > mv){
        unsigned own = __ballot_sync(FULLM, (lane < KNN) && (bd == mv));
        int ml = __ffs(own) - 1;
        if (lane == ml){ bd = d; bi = j; }
    }
    thr = mv;
}

__global__ __launch_bounds__(256) void knn_kernel()
{
    __shared__ float4 pts[NN];
    int tid = threadIdx.x;
    int b = blockIdx.x;
    for (int j = tid; j < NN; j += 256)
        pts[j] = g_pts[(size_t)b*NN + j];
    __syncthreads();

    int w = tid >> 5, lane = tid & 31;
    int i = blockIdx.y*8 + w;
    float4 q = pts[i];
    float qx2 = 2.f*q.x, qy2 = 2.f*q.y, qz2 = 2.f*q.z, qw = q.w;

    float bd = -CUDART_INF_F;   // valid for lane < 20
    int   bi = 0;
    float thr = -CUDART_INF_F;  // lower bound on current 20th-best

    for (int ch = 0; ch < NN/64; ch++){
        int j0 = ch*64 + lane;
        float4 p0 = pts[j0];
        float4 p1 = pts[j0 + 32];
        float t0 = fmaf(qz2, p0.z, -qw);
        t0 = fmaf(qy2, p0.y, t0);
        t0 = fmaf(qx2, p0.x, t0);
        float nd0 = t0 - p0.w;
        float t1 = fmaf(qz2, p1.z, -qw);
        t1 = fmaf(qy2, p1.y, t1);
        t1 = fmaf(qx2, p1.x, t1);
        float nd1 = t1 - p1.w;

        unsigned mask = __ballot_sync(FULLM, nd0 > thr);
        while (mask){
            int src = __ffs(mask) - 1;
            mask &= mask - 1;
            float d = __shfl_sync(FULLM, nd0, src);
            if (d > thr) warp_insert(d, j0 - lane + src, lane, bd, bi, thr);
        }
        mask = __ballot_sync(FULLM, nd1 > thr);
        while (mask){
            int src = __ffs(mask) - 1;
            mask &= mask - 1;
            float d = __shfl_sync(FULLM, nd1, src);
            if (d > thr) warp_insert(d, j0 - lane + 32 + src, lane, bd, bi, thr);
        }
    }
    if (lane < KNN)
        g_idx[((size_t)b*NN + i)*KNN + lane] = bi;
}

// ---------------- gemmYT v2: Y' = s*(x@Wlo^T), T' = s*(x@Wd^T)+b -----------
template<int C, int SEL>
__global__ __launch_bounds__(256) void gemmYT_kernel(
    const float* __restrict__ x, const float* __restrict__ W,
    const float* __restrict__ bng, const float* __restrict__ bnb,
    const float* __restrict__ bnm, const float* __restrict__ bnv)
{
    const float* __restrict__ xin = (SEL == 0) ? x : (SEL == 1) ? g_x1 : g_x2;

    __shared__ __align__(16) float Wlo[C*64];
    __shared__ __align__(16) float Wd [C*64];
    __shared__ __align__(16) float xS [32*C];

    int tid = threadIdx.x;
    int pt0 = blockIdx.x*32;

    for (int t = tid; t < C*64; t += 256){
        int o = t & 63, c = t >> 6;
        float lo = W[(size_t)o*(2*C) + c];
        Wlo[c*64 + o] = lo;
        Wd [c*64 + o] = W[(size_t)o*(2*C) + C + c] - lo;
    }
    for (int t = tid; t < 32*C; t += 256){
        int p = t / C, c = t % C;
        xS[p*C + c] = xin[((size_t)pt0 + p)*C + c];
    }
    __syncthreads();

    int o0 = (tid & 15)*4;
    int p0 = (tid >> 4)*2, p1 = p0 + 1;

    float aY0[4]={0,0,0,0}, aT0[4]={0,0,0,0};
    float aY1[4]={0,0,0,0}, aT1[4]={0,0,0,0};

#pragma unroll 4
    for (int c = 0; c < C; c++){
        float4 wl = *(const float4*)&Wlo[c*64 + o0];
        float4 wd = *(const float4*)&Wd [c*64 + o0];
        float x0 = xS[p0*C + c];
        float x1 = xS[p1*C + c];
        aY0[0]=fmaf(x0,wl.x,aY0[0]); aY0[1]=fmaf(x0,wl.y,aY0[1]);
        aY0[2]=fmaf(x0,wl.z,aY0[2]); aY0[3]=fmaf(x0,wl.w,aY0[3]);
        aT0[0]=fmaf(x0,wd.x,aT0[0]); aT0[1]=fmaf(x0,wd.y,aT0[1]);
        aT0[2]=fmaf(x0,wd.z,aT0[2]); aT0[3]=fmaf(x0,wd.w,aT0[3]);
        aY1[0]=fmaf(x1,wl.x,aY1[0]); aY1[1]=fmaf(x1,wl.y,aY1[1]);
        aY1[2]=fmaf(x1,wl.z,aY1[2]); aY1[3]=fmaf(x1,wl.w,aY1[3]);
        aT1[0]=fmaf(x1,wd.x,aT1[0]); aT1[1]=fmaf(x1,wd.y,aT1[1]);
        aT1[2]=fmaf(x1,wd.z,aT1[2]); aT1[3]=fmaf(x1,wd.w,aT1[3]);
    }

    float4 gv = *(const float4*)&bng[o0];
    float4 bv = *(const float4*)&bnb[o0];
    float4 mv = *(const float4*)&bnm[o0];
    float4 vv = *(const float4*)&bnv[o0];
    float s[4], bo[4];
    s[0] = gv.x*rsqrtf(vv.x + EPSB); bo[0] = bv.x - mv.x*s[0];
    s[1] = gv.y*rsqrtf(vv.y + EPSB); bo[1] = bv.y - mv.y*s[1];
    s[2] = gv.z*rsqrtf(vv.z + EPSB); bo[2] = bv.z - mv.z*s[2];
    s[3] = gv.w*rsqrtf(vv.w + EPSB); bo[3] = bv.w - mv.w*s[3];

    float4 r;
    r = make_float4(s[0]*aY0[0], s[1]*aY0[1], s[2]*aY0[2], s[3]*aY0[3]);
    *(float4*)&g_Y[((size_t)pt0 + p0)*64 + o0] = r;
    r = make_float4(s[0]*aY1[0], s[1]*aY1[1], s[2]*aY1[2], s[3]*aY1[3]);
    *(float4*)&g_Y[((size_t)pt0 + p1)*64 + o0] = r;
    r = make_float4(fmaf(s[0],aT0[0],bo[0]), fmaf(s[1],aT0[1],bo[1]),
                    fmaf(s[2],aT0[2],bo[2]), fmaf(s[3],aT0[3],bo[3]));
    *(float4*)&g_T[((size_t)pt0 + p0)*64 + o0] = r;
    r = make_float4(fmaf(s[0],aT1[0],bo[0]), fmaf(s[1],aT1[1],bo[1]),
                    fmaf(s[2],aT1[2],bo[2]), fmaf(s[3],aT1[3],bo[3]));
    *(float4*)&g_T[((size_t)pt0 + p1)*64 + o0] = r;
}

// ---------------- edge_conv2: h1=lrelu(Y'[j]+T'[i]) tile -> conv-b -> k-max -
template<int SEL_OUT>
__global__ __launch_bounds__(512) void edge_conv2_kernel(
    const float* __restrict__ Wb,
    const float* __restrict__ bng, const float* __restrict__ bnb,
    const float* __restrict__ bnm, const float* __restrict__ bnv)
{
    float* __restrict__ xout = (SEL_OUT == 1) ? g_x1 : g_x2;

    __shared__ __align__(16) float Ws[64*64];
    __shared__ __align__(16) float As[64*161];
    __shared__ __align__(16) float red[4*8*64];
    __shared__ int idxS[160];

    int tid = threadIdx.x;
    int pt0 = blockIdx.x*8;

    for (int t = tid; t < 4096; t += 512){
        int o = t & 63, c = t >> 6;
        Ws[c*64 + o] = Wb[(size_t)o*64 + c];
    }
    if (tid < 160) idxS[tid] = g_idx[(size_t)pt0*KNN + tid];
    __syncthreads();

    for (int e = tid; e < 160*64; e += 512){
        int r = e >> 6, c = e & 63;
        int p = r / KNN;
        int bb = (pt0 + p) >> 11;
        int j = idxS[r];
        float v = g_Y[((size_t)bb*NN + j)*64 + c] + g_T[((size_t)pt0 + p)*64 + c];
        As[c*161 + r] = lrelu(v);
    }

    int r5 = tid & 31;
    int tn = tid >> 5;
    int o0 = tn*4;

    float s2[4], b2[4];
#pragma unroll
    for (int q = 0; q < 4; q++){
        int o = o0 + q;
        float r = rsqrtf(bnv[o] + EPSB);
        s2[q] = bng[o]*r; b2[q] = bnb[o] - bnm[o]*s2[q];
    }
    __syncthreads();

    float acc[5][4];
#pragma unroll
    for (int i = 0; i < 5; i++)
#pragma unroll
        for (int q = 0; q < 4; q++) acc[i][q] = 0.f;

#pragma unroll 4
    for (int c = 0; c < 64; c++){
        float4 w = *(const float4*)&Ws[c*64 + o0];
        float a0 = As[c*161 + r5*5 + 0];
        float a1 = As[c*161 + r5*5 + 1];
        float a2 = As[c*161 + r5*5 + 2];
        float a3 = As[c*161 + r5*5 + 3];
        float a4 = As[c*161 + r5*5 + 4];
        acc[0][0]=fmaf(a0,w.x,acc[0][0]); acc[0][1]=fmaf(a0,w.y,acc[0][1]);
        acc[0][2]=fmaf(a0,w.z,acc[0][2]); acc[0][3]=fmaf(a0,w.w,acc[0][3]);
        acc[1][0]=fmaf(a1,w.x,acc[1][0]); acc[1][1]=fmaf(a1,w.y,acc[1][1]);
        acc[1][2]=fmaf(a1,w.z,acc[1][2]); acc[1][3]=fmaf(a1,w.w,acc[1][3]);
        acc[2][0]=fmaf(a2,w.x,acc[2][0]); acc[2][1]=fmaf(a2,w.y,acc[2][1]);
        acc[2][2]=fmaf(a2,w.z,acc[2][2]); acc[2][3]=fmaf(a2,w.w,acc[2][3]);
        acc[3][0]=fmaf(a3,w.x,acc[3][0]); acc[3][1]=fmaf(a3,w.y,acc[3][1]);
        acc[3][2]=fmaf(a3,w.z,acc[3][2]); acc[3][3]=fmaf(a3,w.w,acc[3][3]);
        acc[4][0]=fmaf(a4,w.x,acc[4][0]); acc[4][1]=fmaf(a4,w.y,acc[4][1]);
        acc[4][2]=fmaf(a4,w.z,acc[4][2]); acc[4][3]=fmaf(a4,w.w,acc[4][3]);
    }

    int p    = r5 >> 2;
    int part = r5 & 3;
#pragma unroll
    for (int q = 0; q < 4; q++){
        float mx = -CUDART_INF_F;
#pragma unroll
        for (int i = 0; i < 5; i++)
            mx = fmaxf(mx, lrelu(fmaf(acc[i][q], s2[q], b2[q])));
        red[(part*8 + p)*64 + o0 + q] = mx;
    }
    __syncthreads();

    {
        int pp = tid >> 6, oo = tid & 63;
        float m = red[(0*8 + pp)*64 + oo];
        m = fmaxf(m, red[(1*8 + pp)*64 + oo]);
        m = fmaxf(m, red[(2*8 + pp)*64 + oo]);
        m = fmaxf(m, red[(3*8 + pp)*64 + oo]);
        xout[((size_t)pt0 + pp)*64 + oo] = m;
    }
}

// ---------------- edge_max (stage 3): x3 = max_k lrelu(Y'[j]+T'[i]) --------
__global__ __launch_bounds__(256) void edge_max_kernel()
{
    __shared__ int idxS[4*KNN];
    int tid = threadIdx.x;
    int pt0 = blockIdx.x*4;
    if (tid < 4*KNN) idxS[tid] = g_idx[(size_t)pt0*KNN + tid];
    __syncthreads();

    int p = tid >> 6, o = tid & 63;
    int pt = pt0 + p;
    int bb = pt >> 11;
    float tv = g_T[(size_t)pt*64 + o];
    float m = -CUDART_INF_F;
#pragma unroll
    for (int k = 0; k < KNN; k++){
        int j = idxS[p*KNN + k];
        m = fmaxf(m, lrelu(g_Y[((size_t)bb*NN + j)*64 + o] + tv));
    }
    g_x3[(size_t)pt*64 + o] = m;
}

// ---------------- init / final GEMM v2 / outputs ---------------------------
__global__ void init_gmax_kernel(){
    int t = blockIdx.x*256 + threadIdx.x;
    if (t < BB*1024) g_gmax[t] = 0u;
}

__global__ __launch_bounds__(256) void final_kernel(
    const float* __restrict__ W6,
    const float* __restrict__ bn6g, const float* __restrict__ bn6b,
    const float* __restrict__ bn6m, const float* __restrict__ bn6v)
{
    extern __shared__ float dsm[];
    float* Bs = dsm;              // [192*68]
    float* As = dsm + 192*68;     // [192*68]
    __shared__ float ss6[64], sb6[64];
    __shared__ float red[64*16];

    int tid = threadIdx.x;
    int n0 = blockIdx.x*64;
    int bb = blockIdx.y;
    int mc = blockIdx.z;

    if (tid < 64){
        int o = n0 + tid;
        float r = rsqrtf(bn6v[o] + EPSB);
        ss6[tid] = bn6g[o]*r; sb6[tid] = bn6b[o] - bn6m[o]*ss6[tid];
    }

    for (int ch = 0; ch < 3; ch++)
        for (int t = tid; t < 4096; t += 256){
            int nn = t >> 6, c = t & 63;
            Bs[(ch*64 + c)*68 + nn] = W6[(size_t)(n0+nn)*192 + ch*64 + c];
        }
    __syncthreads();

    int tm = tid & 15, tn = tid >> 4;
    float s6[4], b6[4];
#pragma unroll
    for (int q = 0; q < 4; q++){ s6[q] = ss6[tn*4+q]; b6[q] = sb6[tn*4+q]; }

    float vmax[4] = {-CUDART_INF_F, -CUDART_INF_F, -CUDART_INF_F, -CUDART_INF_F};

    for (int mi = mc*8; mi < mc*8 + 8; mi++){
        size_t m1 = (size_t)bb*NN + mi*64;
        __syncthreads();
        {
            for (int t = tid; t < 4096; t += 256){
                int m = t >> 6, c = t & 63;
                As[(0*64 + c)*68 + m] = g_x1[(m1 + m)*64 + c];
            }
            for (int t = tid; t < 4096; t += 256){
                int m = t >> 6, c = t & 63;
                As[(1*64 + c)*68 + m] = g_x2[(m1 + m)*64 + c];
            }
            for (int t = tid; t < 4096; t += 256){
                int m = t >> 6, c = t & 63;
                As[(2*64 + c)*68 + m] = g_x3[(m1 + m)*64 + c];
            }
        }
        __syncthreads();

        float acc[4][4];
#pragma unroll
        for (int i = 0; i < 4; i++)
#pragma unroll
            for (int j = 0; j < 4; j++) acc[i][j] = 0.f;

#pragma unroll 8
        for (int c = 0; c < 192; c++){
            float4 a  = *(const float4*)&As[c*68 + tm*4];
            float4 bv = *(const float4*)&Bs[c*68 + tn*4];
            acc[0][0] = fmaf(a.x,bv.x,acc[0][0]); acc[0][1] = fmaf(a.x,bv.y,acc[0][1]);
            acc[0][2] = fmaf(a.x,bv.z,acc[0][2]); acc[0][3] = fmaf(a.x,bv.w,acc[0][3]);
            acc[1][0] = fmaf(a.y,bv.x,acc[1][0]); acc[1][1] = fmaf(a.y,bv.y,acc[1][1]);
            acc[1][2] = fmaf(a.y,bv.z,acc[1][2]); acc[1][3] = fmaf(a.y,bv.w,acc[1][3]);
            acc[2][0] = fmaf(a.z,bv.x,acc[2][0]); acc[2][1] = fmaf(a.z,bv.y,acc[2][1]);
            acc[2][2] = fmaf(a.z,bv.z,acc[2][2]); acc[2][3] = fmaf(a.z,bv.w,acc[2][3]);
            acc[3][0] = fmaf(a.w,bv.x,acc[3][0]); acc[3][1] = fmaf(a.w,bv.y,acc[3][1]);
            acc[3][2] = fmaf(a.w,bv.z,acc[3][2]); acc[3][3] = fmaf(a.w,bv.w,acc[3][3]);
        }
#pragma unroll
        for (int nq = 0; nq < 4; nq++)
#pragma unroll
            for (int mq = 0; mq < 4; mq++)
                vmax[nq] = fmaxf(vmax[nq], lrelu(fmaf(acc[mq][nq], s6[nq], b6[nq])));
    }

    __syncthreads();
#pragma unroll
    for (int nq = 0; nq < 4; nq++) red[(tn*4+nq)*16 + tm] = vmax[nq];
    __syncthreads();
    if (tid < 64){
        float mx = -CUDART_INF_F;
#pragma unroll
        for (int t = 0; t < 16; t++) mx = fmaxf(mx, red[tid*16 + t]);
        atomicMax(&g_gmax[bb*1024 + n0 + tid], fenc(mx));
    }
}

__global__ void feat_kernel(float* __restrict__ out){
    int t = blockIdx.x*256 + threadIdx.x;
    if (t < BB*1024) out[t] = fdec(g_gmax[t]);
}

// ---------------- x4^T via smem transpose ----------------------------------
__global__ __launch_bounds__(256) void x4t_kernel(float* __restrict__ out)
{
    __shared__ float T[64*65];
    int tid = threadIdx.x;
    int n0 = blockIdx.x*64;
    int bb = blockIdx.y;
    int ch = blockIdx.z;
    const float* src = (ch == 0) ? g_x1 : (ch == 1) ? g_x2 : g_x3;

    for (int t = tid; t < 4096; t += 256){
        int c = t & 63, n = t >> 6;
        T[c*65 + n] = src[((size_t)bb*NN + n0 + n)*64 + c];
    }
    __syncthreads();
    size_t base = (size_t)BB*1024 + (size_t)bb*192*NN + (size_t)ch*64*NN;
    for (int t = tid; t < 4096; t += 256){
        int n = t & 63, c = t >> 6;
        out[base + (size_t)c*NN + n0 + n] = T[c*65 + n];
    }
}

// ---------------- launch ----------------------------------------------------
extern "C" void kernel_launch(void* const* d_in, const int* in_sizes, int n_in,
                              void* d_out, int out_size)
{
    const float* x    = (const float*)d_in[0];
    const float* W1   = (const float*)d_in[1];
    const float* W2   = (const float*)d_in[2];
    const float* W3   = (const float*)d_in[3];
    const float* W4   = (const float*)d_in[4];
    const float* W5   = (const float*)d_in[5];
    const float* W6   = (const float*)d_in[6];
    const float* bng  = (const float*)d_in[7];
    const float* bnb  = (const float*)d_in[8];
    const float* bnm  = (const float*)d_in[9];
    const float* bnv  = (const float*)d_in[10];
    const float* bn6g = (const float*)d_in[11];
    const float* bn6b = (const float*)d_in[12];
    const float* bn6m = (const float*)d_in[13];
    const float* bn6v = (const float*)d_in[14];
    float* out = (float*)d_out;

    cudaFuncSetAttribute(final_kernel,
        cudaFuncAttributeMaxDynamicSharedMemorySize, 2*192*68*4);
    const int FSMEM = 2*192*68*4;

    // Stage 1                                                       (launch idx)
    prep_pts_kernel<0><<<NTOT/256, 256>>>(x);                                 // 0
    gemmYT_kernel<3,0><<<NTOT/32, 256>>>(x, W1, bng, bnb, bnm, bnv);          // 1
    init_gmax_kernel<<<32, 256>>>();                                          // 2
    knn_kernel<<<dim3(BB, NN/8), 256>>>();                                    // 3  <- ncu capture
    edge_conv2_kernel<1><<<NTOT/8, 512>>>(W2, bng+64, bnb+64, bnm+64, bnv+64);// 4

    // Stage 2
    prep_pts_kernel<1><<<NTOT/256, 256>>>(x);                                 // 5
    knn_kernel<<<dim3(BB, NN/8), 256>>>();                                    // 6
    gemmYT_kernel<64,1><<<NTOT/32, 256>>>(x, W3, bng+2*64, bnb+2*64, bnm+2*64, bnv+2*64); // 7
    edge_conv2_kernel<2><<<NTOT/8, 512>>>(W4, bng+3*64, bnb+3*64, bnm+3*64, bnv+3*64);    // 8

    // Stage 3
    prep_pts_kernel<2><<<NTOT/256, 256>>>(x);                                 // 9
    knn_kernel<<<dim3(BB, NN/8), 256>>>();                                    // 10
    gemmYT_kernel<64,2><<<NTOT/32, 256>>>(x, W5, bng+4*64, bnb+4*64, bnm+4*64, bnv+4*64); // 11
    edge_max_kernel<<<NTOT/4, 256>>>();                                       // 12

    // Final block + global max pool
    final_kernel<<<dim3(1024/64, BB, 4), 256, FSMEM>>>(W6, bn6g, bn6b, bn6m, bn6v);
    feat_kernel<<<32, 256>>>(out);
    x4t_kernel<<<dim3(NN/64, BB, 3), 256>>>(out);
}

// round 11
// speedup vs baseline: 2.7191x; 1.1559x over previous
#include <cuda_runtime.h>
#include <math_constants.h>

#define BB 8
#define NN 2048
#define KNN 20
#define NTOT (BB*NN)
#define EPSB 1e-5f
#define FULLM 0xFFFFFFFFu
#define ENC_NEGINF 0x007FFFFFu   // fenc(-INF)

// ---------------- scratch (device globals; no allocation allowed) ----------
__device__ int      g_idx[NTOT*KNN];
__device__ float    g_x1[NTOT*64];
__device__ float    g_x2[NTOT*64];
__device__ float    g_x3[NTOT*64];
__device__ float    g_Y[NTOT*64];
__device__ float    g_T[NTOT*64];
__device__ float4   g_pts[NTOT];
__device__ unsigned g_gmax[BB*1024];

__device__ __forceinline__ float lrelu(float z){ return z >= 0.f ? z : 0.2f*z; }
__device__ __forceinline__ unsigned fenc(float f){
    unsigned u = __float_as_uint(f);
    return u ^ ((unsigned)((int)u >> 31) | 0x80000000u);   // SHF + LOP3
}
__device__ __forceinline__ unsigned fencs(float f){        // for gmax path
    unsigned u = __float_as_uint(f);
    return (u & 0x80000000u) ? ~u : (u | 0x80000000u);
}
__device__ __forceinline__ float fdec(unsigned e){
    return (e & 0x80000000u) ? __uint_as_float(e ^ 0x80000000u) : __uint_as_float(~e);
}

// ---------------- prep: pack knn source coords as float4 (x,y,z,|p|^2) -----
template<int SEL>
__global__ __launch_bounds__(256) void prep_pts_kernel(const float* __restrict__ x)
{
    int t = blockIdx.x*256 + threadIdx.x;
    if (t >= NTOT) return;
    const float* src = (SEL == 0) ? (x + (size_t)t*3)
                                  : (((SEL == 1) ? g_x1 : g_x2) + (size_t)t*64 + 6);
    float px = src[0], py = src[1], pz = src[2];
    g_pts[t] = make_float4(px, py, pz, px*px + py*py + pz*pz);
}

// ---------------- kNN v7: warp-per-query, enc-domain + redux inserts -------
// grid (BB, NN/8), 256 thr = 8 warps = 8 queries/block. Lanes 0..19 hold the
// unsorted top-20 as fenc() codes (order-preserving unsigned). Lanes 20..31
// hold 0xFFFFFFFF so they never win the min. One __reduce_min_sync per insert.
__global__ __launch_bounds__(256) void knn_kernel()
{
    __shared__ float4 pts[NN];
    int tid = threadIdx.x;
    int b = blockIdx.x;
    for (int j = tid; j < NN; j += 256)
        pts[j] = g_pts[(size_t)b*NN + j];
    __syncthreads();

    int w = tid >> 5, lane = tid & 31;
    int i = blockIdx.y*8 + w;
    float4 q = pts[i];
    float qx2 = 2.f*q.x, qy2 = 2.f*q.y, qz2 = 2.f*q.z, qw = q.w;

    unsigned be  = (lane < KNN) ? ENC_NEGINF : 0xFFFFFFFFu;
    int      bi  = 0;
    unsigned thr = ENC_NEGINF;   // enc of current lower bound on 20th-best

    for (int ch = 0; ch < NN/64; ch++){
        int j0 = ch*64 + lane;
        float4 p0 = pts[j0];
        float4 p1 = pts[j0 + 32];
        float t0 = fmaf(qz2, p0.z, -qw);
        t0 = fmaf(qy2, p0.y, t0);
        t0 = fmaf(qx2, p0.x, t0);
        unsigned e0 = fenc(t0 - p0.w);
        float t1 = fmaf(qz2, p1.z, -qw);
        t1 = fmaf(qy2, p1.y, t1);
        t1 = fmaf(qx2, p1.x, t1);
        unsigned e1 = fenc(t1 - p1.w);

        unsigned mask = __ballot_sync(FULLM, e0 > thr);
        while (mask){
            int src = __ffs(mask) - 1;
            mask &= mask - 1;
            unsigned e = __shfl_sync(FULLM, e0, src);
            if (e > thr){
                unsigned mv = __reduce_min_sync(FULLM, be);
                if (e > mv){
                    unsigned own = __ballot_sync(FULLM, be == mv);
                    int ml = __ffs(own) - 1;
                    if (lane == ml){ be = e; bi = j0 - lane + src; }
                }
                thr = mv;    // pre-insert min: safe lower bound
            }
        }
        mask = __ballot_sync(FULLM, e1 > thr);
        while (mask){
            int src = __ffs(mask) - 1;
            mask &= mask - 1;
            unsigned e = __shfl_sync(FULLM, e1, src);
            if (e > thr){
                unsigned mv = __reduce_min_sync(FULLM, be);
                if (e > mv){
                    unsigned own = __ballot_sync(FULLM, be == mv);
                    int ml = __ffs(own) - 1;
                    if (lane == ml){ be = e; bi = j0 - lane + 32 + src; }
                }
                thr = mv;
            }
        }
    }
    if (lane < KNN)
        g_idx[((size_t)b*NN + i)*KNN + lane] = bi;
}

// ---------------- gemmYT v2: Y' = s*(x@Wlo^T), T' = s*(x@Wd^T)+b -----------
template<int C, int SEL>
__global__ __launch_bounds__(256) void gemmYT_kernel(
    const float* __restrict__ x, const float* __restrict__ W,
    const float* __restrict__ bng, const float* __restrict__ bnb,
    const float* __restrict__ bnm, const float* __restrict__ bnv)
{
    const float* __restrict__ xin = (SEL == 0) ? x : (SEL == 1) ? g_x1 : g_x2;

    __shared__ __align__(16) float Wlo[C*64];
    __shared__ __align__(16) float Wd [C*64];
    __shared__ __align__(16) float xS [32*C];

    int tid = threadIdx.x;
    int pt0 = blockIdx.x*32;

    for (int t = tid; t < C*64; t += 256){
        int o = t & 63, c = t >> 6;
        float lo = W[(size_t)o*(2*C) + c];
        Wlo[c*64 + o] = lo;
        Wd [c*64 + o] = W[(size_t)o*(2*C) + C + c] - lo;
    }
    for (int t = tid; t < 32*C; t += 256){
        int p = t / C, c = t % C;
        xS[p*C + c] = xin[((size_t)pt0 + p)*C + c];
    }
    __syncthreads();

    int o0 = (tid & 15)*4;
    int p0 = (tid >> 4)*2, p1 = p0 + 1;

    float aY0[4]={0,0,0,0}, aT0[4]={0,0,0,0};
    float aY1[4]={0,0,0,0}, aT1[4]={0,0,0,0};

#pragma unroll 4
    for (int c = 0; c < C; c++){
        float4 wl = *(const float4*)&Wlo[c*64 + o0];
        float4 wd = *(const float4*)&Wd [c*64 + o0];
        float x0 = xS[p0*C + c];
        float x1 = xS[p1*C + c];
        aY0[0]=fmaf(x0,wl.x,aY0[0]); aY0[1]=fmaf(x0,wl.y,aY0[1]);
        aY0[2]=fmaf(x0,wl.z,aY0[2]); aY0[3]=fmaf(x0,wl.w,aY0[3]);
        aT0[0]=fmaf(x0,wd.x,aT0[0]); aT0[1]=fmaf(x0,wd.y,aT0[1]);
        aT0[2]=fmaf(x0,wd.z,aT0[2]); aT0[3]=fmaf(x0,wd.w,aT0[3]);
        aY1[0]=fmaf(x1,wl.x,aY1[0]); aY1[1]=fmaf(x1,wl.y,aY1[1]);
        aY1[2]=fmaf(x1,wl.z,aY1[2]); aY1[3]=fmaf(x1,wl.w,aY1[3]);
        aT1[0]=fmaf(x1,wd.x,aT1[0]); aT1[1]=fmaf(x1,wd.y,aT1[1]);
        aT1[2]=fmaf(x1,wd.z,aT1[2]); aT1[3]=fmaf(x1,wd.w,aT1[3]);
    }

    float4 gv = *(const float4*)&bng[o0];
    float4 bv = *(const float4*)&bnb[o0];
    float4 mv = *(const float4*)&bnm[o0];
    float4 vv = *(const float4*)&bnv[o0];
    float s[4], bo[4];
    s[0] = gv.x*rsqrtf(vv.x + EPSB); bo[0] = bv.x - mv.x*s[0];
    s[1] = gv.y*rsqrtf(vv.y + EPSB); bo[1] = bv.y - mv.y*s[1];
    s[2] = gv.z*rsqrtf(vv.z + EPSB); bo[2] = bv.z - mv.z*s[2];
    s[3] = gv.w*rsqrtf(vv.w + EPSB); bo[3] = bv.w - mv.w*s[3];

    float4 r;
    r = make_float4(s[0]*aY0[0], s[1]*aY0[1], s[2]*aY0[2], s[3]*aY0[3]);
    *(float4*)&g_Y[((size_t)pt0 + p0)*64 + o0] = r;
    r = make_float4(s[0]*aY1[0], s[1]*aY1[1], s[2]*aY1[2], s[3]*aY1[3]);
    *(float4*)&g_Y[((size_t)pt0 + p1)*64 + o0] = r;
    r = make_float4(fmaf(s[0],aT0[0],bo[0]), fmaf(s[1],aT0[1],bo[1]),
                    fmaf(s[2],aT0[2],bo[2]), fmaf(s[3],aT0[3],bo[3]));
    *(float4*)&g_T[((size_t)pt0 + p0)*64 + o0] = r;
    r = make_float4(fmaf(s[0],aT1[0],bo[0]), fmaf(s[1],aT1[1],bo[1]),
                    fmaf(s[2],aT1[2],bo[2]), fmaf(s[3],aT1[3],bo[3]));
    *(float4*)&g_T[((size_t)pt0 + p1)*64 + o0] = r;
}

// ---------------- edge_conv2 v2: 256 thr, 5x8 micro-tile -------------------
// 8 points (160 rows)/block. thread = (r5 = tid&31 -> rows 5r5..5r5+4,
//                                      og = (tid>>5)*8 -> 8 outputs)
template<int SEL_OUT>
__global__ __launch_bounds__(256) void edge_conv2_kernel(
    const float* __restrict__ Wb,
    const float* __restrict__ bng, const float* __restrict__ bnb,
    const float* __restrict__ bnm, const float* __restrict__ bnv)
{
    float* __restrict__ xout = (SEL_OUT == 1) ? g_x1 : g_x2;

    __shared__ __align__(16) float Ws[64*64];
    __shared__ __align__(16) float As[64*161];
    __shared__ __align__(16) float red[4*8*64];
    __shared__ int idxS[160];

    int tid = threadIdx.x;
    int pt0 = blockIdx.x*8;

    for (int t = tid; t < 4096; t += 256){
        int o = t & 63, c = t >> 6;
        Ws[c*64 + o] = Wb[(size_t)o*64 + c];
    }
    if (tid < 160) idxS[tid] = g_idx[(size_t)pt0*KNN + tid];
    __syncthreads();

    for (int e = tid; e < 160*64; e += 256){
        int r = e >> 6, c = e & 63;
        int p = r / KNN;
        int bb = (pt0 + p) >> 11;
        int j = idxS[r];
        float v = g_Y[((size_t)bb*NN + j)*64 + c] + g_T[((size_t)pt0 + p)*64 + c];
        As[c*161 + r] = lrelu(v);
    }

    int r5 = tid & 31;
    int og = (tid >> 5) * 8;

    float s2[8], b2[8];
#pragma unroll
    for (int q = 0; q < 8; q++){
        int o = og + q;
        float r = rsqrtf(bnv[o] + EPSB);
        s2[q] = bng[o]*r; b2[q] = bnb[o] - bnm[o]*s2[q];
    }
    __syncthreads();

    float acc[5][8];
#pragma unroll
    for (int i = 0; i < 5; i++)
#pragma unroll
        for (int q = 0; q < 8; q++) acc[i][q] = 0.f;

#pragma unroll 4
    for (int c = 0; c < 64; c++){
        float4 wA = *(const float4*)&Ws[c*64 + og];
        float4 wB = *(const float4*)&Ws[c*64 + og + 4];
        float a[5];
#pragma unroll
        for (int i = 0; i < 5; i++) a[i] = As[c*161 + r5*5 + i];
#pragma unroll
        for (int i = 0; i < 5; i++){
            acc[i][0]=fmaf(a[i],wA.x,acc[i][0]); acc[i][1]=fmaf(a[i],wA.y,acc[i][1]);
            acc[i][2]=fmaf(a[i],wA.z,acc[i][2]); acc[i][3]=fmaf(a[i],wA.w,acc[i][3]);
            acc[i][4]=fmaf(a[i],wB.x,acc[i][4]); acc[i][5]=fmaf(a[i],wB.y,acc[i][5]);
            acc[i][6]=fmaf(a[i],wB.z,acc[i][6]); acc[i][7]=fmaf(a[i],wB.w,acc[i][7]);
        }
    }

    int p    = r5 >> 2;
    int part = r5 & 3;
#pragma unroll
    for (int q = 0; q < 8; q++){
        float mx = -CUDART_INF_F;
#pragma unroll
        for (int i = 0; i < 5; i++)
            mx = fmaxf(mx, lrelu(fmaf(acc[i][q], s2[q], b2[q])));
        red[(part*8 + p)*64 + og + q] = mx;
    }
    __syncthreads();

    for (int t = tid; t < 512; t += 256){
        int pp = t >> 6, oo = t & 63;
        float m = red[(0*8 + pp)*64 + oo];
        m = fmaxf(m, red[(1*8 + pp)*64 + oo]);
        m = fmaxf(m, red[(2*8 + pp)*64 + oo]);
        m = fmaxf(m, red[(3*8 + pp)*64 + oo]);
        xout[((size_t)pt0 + pp)*64 + oo] = m;
    }
}

// ---------------- edge_max (stage 3): x3 = max_k lrelu(Y'[j]+T'[i]) --------
__global__ __launch_bounds__(256) void edge_max_kernel()
{
    __shared__ int idxS[4*KNN];
    int tid = threadIdx.x;
    int pt0 = blockIdx.x*4;
    if (tid < 4*KNN) idxS[tid] = g_idx[(size_t)pt0*KNN + tid];
    __syncthreads();

    int p = tid >> 6, o = tid & 63;
    int pt = pt0 + p;
    int bb = pt >> 11;
    float tv = g_T[(size_t)pt*64 + o];
    float m = -CUDART_INF_F;
#pragma unroll
    for (int k = 0; k < KNN; k++){
        int j = idxS[p*KNN + k];
        m = fmaxf(m, lrelu(g_Y[((size_t)bb*NN + j)*64 + o] + tv));
    }
    g_x3[(size_t)pt*64 + o] = m;
}

// ---------------- init / final GEMM v2 / outputs ---------------------------
__global__ void init_gmax_kernel(){
    int t = blockIdx.x*256 + threadIdx.x;
    if (t < BB*1024) g_gmax[t] = 0u;
}

__global__ __launch_bounds__(256) void final_kernel(
    const float* __restrict__ W6,
    const float* __restrict__ bn6g, const float* __restrict__ bn6b,
    const float* __restrict__ bn6m, const float* __restrict__ bn6v)
{
    extern __shared__ float dsm[];
    float* Bs = dsm;              // [192*68]
    float* As = dsm + 192*68;     // [192*68]
    __shared__ float ss6[64], sb6[64];
    __shared__ float red[64*16];

    int tid = threadIdx.x;
    int n0 = blockIdx.x*64;
    int bb = blockIdx.y;
    int mc = blockIdx.z;

    if (tid < 64){
        int o = n0 + tid;
        float r = rsqrtf(bn6v[o] + EPSB);
        ss6[tid] = bn6g[o]*r; sb6[tid] = bn6b[o] - bn6m[o]*ss6[tid];
    }

    for (int ch = 0; ch < 3; ch++)
        for (int t = tid; t < 4096; t += 256){
            int nn = t >> 6, c = t & 63;
            Bs[(ch*64 + c)*68 + nn] = W6[(size_t)(n0+nn)*192 + ch*64 + c];
        }
    __syncthreads();

    int tm = tid & 15, tn = tid >> 4;
    float s6[4], b6[4];
#pragma unroll
    for (int q = 0; q < 4; q++){ s6[q] = ss6[tn*4+q]; b6[q] = sb6[tn*4+q]; }

    float vmax[4] = {-CUDART_INF_F, -CUDART_INF_F, -CUDART_INF_F, -CUDART_INF_F};

    for (int mi = mc*8; mi < mc*8 + 8; mi++){
        size_t m1 = (size_t)bb*NN + mi*64;
        __syncthreads();
        {
            for (int t = tid; t < 4096; t += 256){
                int m = t >> 6, c = t & 63;
                As[(0*64 + c)*68 + m] = g_x1[(m1 + m)*64 + c];
            }
            for (int t = tid; t < 4096; t += 256){
                int m = t >> 6, c = t & 63;
                As[(1*64 + c)*68 + m] = g_x2[(m1 + m)*64 + c];
            }
            for (int t = tid; t < 4096; t += 256){
                int m = t >> 6, c = t & 63;
                As[(2*64 + c)*68 + m] = g_x3[(m1 + m)*64 + c];
            }
        }
        __syncthreads();

        float acc[4][4];
#pragma unroll
        for (int i = 0; i < 4; i++)
#pragma unroll
            for (int j = 0; j < 4; j++) acc[i][j] = 0.f;

#pragma unroll 8
        for (int c = 0; c < 192; c++){
            float4 a  = *(const float4*)&As[c*68 + tm*4];
            float4 bv = *(const float4*)&Bs[c*68 + tn*4];
            acc[0][0] = fmaf(a.x,bv.x,acc[0][0]); acc[0][1] = fmaf(a.x,bv.y,acc[0][1]);
            acc[0][2] = fmaf(a.x,bv.z,acc[0][2]); acc[0][3] = fmaf(a.x,bv.w,acc[0][3]);
            acc[1][0] = fmaf(a.y,bv.x,acc[1][0]); acc[1][1] = fmaf(a.y,bv.y,acc[1][1]);
            acc[1][2] = fmaf(a.y,bv.z,acc[1][2]); acc[1][3] = fmaf(a.y,bv.w,acc[1][3]);
            acc[2][0] = fmaf(a.z,bv.x,acc[2][0]); acc[2][1] = fmaf(a.z,bv.y,acc[2][1]);
            acc[2][2] = fmaf(a.z,bv.z,acc[2][2]); acc[2][3] = fmaf(a.z,bv.w,acc[2][3]);
            acc[3][0] = fmaf(a.w,bv.x,acc[3][0]); acc[3][1] = fmaf(a.w,bv.y,acc[3][1]);
            acc[3][2] = fmaf(a.w,bv.z,acc[3][2]); acc[3][3] = fmaf(a.w,bv.w,acc[3][3]);
        }
#pragma unroll
        for (int nq = 0; nq < 4; nq++)
#pragma unroll
            for (int mq = 0; mq < 4; mq++)
                vmax[nq] = fmaxf(vmax[nq], lrelu(fmaf(acc[mq][nq], s6[nq], b6[nq])));
    }

    __syncthreads();
#pragma unroll
    for (int nq = 0; nq < 4; nq++) red[(tn*4+nq)*16 + tm] = vmax[nq];
    __syncthreads();
    if (tid < 64){
        float mx = -CUDART_INF_F;
#pragma unroll
        for (int t = 0; t < 16; t++) mx = fmaxf(mx, red[tid*16 + t]);
        atomicMax(&g_gmax[bb*1024 + n0 + tid], fencs(mx));
    }
}

__global__ void feat_kernel(float* __restrict__ out){
    int t = blockIdx.x*256 + threadIdx.x;
    if (t < BB*1024) out[t] = fdec(g_gmax[t]);
}

// ---------------- x4^T via smem transpose ----------------------------------
__global__ __launch_bounds__(256) void x4t_kernel(float* __restrict__ out)
{
    __shared__ float T[64*65];
    int tid = threadIdx.x;
    int n0 = blockIdx.x*64;
    int bb = blockIdx.y;
    int ch = blockIdx.z;
    const float* src = (ch == 0) ? g_x1 : (ch == 1) ? g_x2 : g_x3;

    for (int t = tid; t < 4096; t += 256){
        int c = t & 63, n = t >> 6;
        T[c*65 + n] = src[((size_t)bb*NN + n0 + n)*64 + c];
    }
    __syncthreads();
    size_t base = (size_t)BB*1024 + (size_t)bb*192*NN + (size_t)ch*64*NN;
    for (int t = tid; t < 4096; t += 256){
        int n = t & 63, c = t >> 6;
        out[base + (size_t)c*NN + n0 + n] = T[c*65 + n];
    }
}

// ---------------- launch ----------------------------------------------------
extern "C" void kernel_launch(void* const* d_in, const int* in_sizes, int n_in,
                              void* d_out, int out_size)
{
    const float* x    = (const float*)d_in[0];
    const float* W1   = (const float*)d_in[1];
    const float* W2   = (const float*)d_in[2];
    const float* W3   = (const float*)d_in[3];
    const float* W4   = (const float*)d_in[4];
    const float* W5   = (const float*)d_in[5];
    const float* W6   = (const float*)d_in[6];
    const float* bng  = (const float*)d_in[7];
    const float* bnb  = (const float*)d_in[8];
    const float* bnm  = (const float*)d_in[9];
    const float* bnv  = (const float*)d_in[10];
    const float* bn6g = (const float*)d_in[11];
    const float* bn6b = (const float*)d_in[12];
    const float* bn6m = (const float*)d_in[13];
    const float* bn6v = (const float*)d_in[14];
    float* out = (float*)d_out;

    cudaFuncSetAttribute(final_kernel,
        cudaFuncAttributeMaxDynamicSharedMemorySize, 2*192*68*4);
    const int FSMEM = 2*192*68*4;

    // Stage 1                                                       (launch idx)
    prep_pts_kernel<0><<<NTOT/256, 256>>>(x);                                 // 0
    gemmYT_kernel<3,0><<<NTOT/32, 256>>>(x, W1, bng, bnb, bnm, bnv);          // 1
    init_gmax_kernel<<<32, 256>>>();                                          // 2
    knn_kernel<<<dim3(BB, NN/8), 256>>>();                                    // 3  <- ncu capture
    edge_conv2_kernel<1><<<NTOT/8, 256>>>(W2, bng+64, bnb+64, bnm+64, bnv+64);// 4

    // Stage 2
    prep_pts_kernel<1><<<NTOT/256, 256>>>(x);                                 // 5
    knn_kernel<<<dim3(BB, NN/8), 256>>>();                                    // 6
    gemmYT_kernel<64,1><<<NTOT/32, 256>>>(x, W3, bng+2*64, bnb+2*64, bnm+2*64, bnv+2*64); // 7
    edge_conv2_kernel<2><<<NTOT/8, 256>>>(W4, bng+3*64, bnb+3*64, bnm+3*64, bnv+3*64);    // 8

    // Stage 3
    prep_pts_kernel<2><<<NTOT/256, 256>>>(x);                                 // 9
    knn_kernel<<<dim3(BB, NN/8), 256>>>();                                    // 10
    gemmYT_kernel<64,2><<<NTOT/32, 256>>>(x, W5, bng+4*64, bnb+4*64, bnm+4*64, bnv+4*64); // 11
    edge_max_kernel<<<NTOT/4, 256>>>();                                       // 12

    // Final block + global max pool
    final_kernel<<<dim3(1024/64, BB, 4), 256, FSMEM>>>(W6, bn6g, bn6b, bn6m, bn6v);
    feat_kernel<<<32, 256>>>(out);
    x4t_kernel<<<dim3(NN/64, BB, 3), 256>>>(out);
}

// round 12
// speedup vs baseline: 2.7874x; 1.0251x over previous
#include <cuda_runtime.h>
#include <math_constants.h>

#define BB 8
#define NN 2048
#define KNN 20
#define NTOT (BB*NN)
#define EPSB 1e-5f
#define FULLM 0xFFFFFFFFu
#define ENC_NEGINF 0x007FFFFFu   // fenc(-INF)

// ---------------- scratch (device globals; no allocation allowed) ----------
__device__ int      g_idx[NTOT*KNN];
__device__ float    g_x1[NTOT*64];
__device__ float    g_x2[NTOT*64];
__device__ float    g_x3[NTOT*64];
__device__ float    g_Y[NTOT*64];
__device__ float    g_T[NTOT*64];
__device__ float4   g_pts[NTOT];
__device__ unsigned g_gmax[BB*1024];

__device__ __forceinline__ float lrelu(float z){ return z >= 0.f ? z : 0.2f*z; }
__device__ __forceinline__ unsigned fenc(float f){
    unsigned u = __float_as_uint(f);
    return u ^ ((unsigned)((int)u >> 31) | 0x80000000u);   // SHF + LOP3
}
__device__ __forceinline__ unsigned fencs(float f){        // for gmax path
    unsigned u = __float_as_uint(f);
    return (u & 0x80000000u) ? ~u : (u | 0x80000000u);
}
__device__ __forceinline__ float fdec(unsigned e){
    return (e & 0x80000000u) ? __uint_as_float(e ^ 0x80000000u) : __uint_as_float(~e);
}

// ---------------- prep (stage 1 only): pack x as float4 (x,y,z,|p|^2) ------
__global__ __launch_bounds__(256) void prep_pts_kernel(const float* __restrict__ x)
{
    int t = blockIdx.x*256 + threadIdx.x;
    if (t >= NTOT) return;
    const float* src = x + (size_t)t*3;
    float px = src[0], py = src[1], pz = src[2];
    g_pts[t] = make_float4(px, py, pz, px*px + py*py + pz*pz);
}

// ---------------- kNN v7: warp-per-query, enc-domain + redux inserts -------
__global__ __launch_bounds__(256) void knn_kernel()
{
    __shared__ float4 pts[NN];
    int tid = threadIdx.x;
    int b = blockIdx.x;
    for (int j = tid; j < NN; j += 256)
        pts[j] = g_pts[(size_t)b*NN + j];
    __syncthreads();

    int w = tid >> 5, lane = tid & 31;
    int i = blockIdx.y*8 + w;
    float4 q = pts[i];
    float qx2 = 2.f*q.x, qy2 = 2.f*q.y, qz2 = 2.f*q.z, qw = q.w;

    unsigned be  = (lane < KNN) ? ENC_NEGINF : 0xFFFFFFFFu;
    int      bi  = 0;
    unsigned thr = ENC_NEGINF;

    for (int ch = 0; ch < NN/64; ch++){
        int j0 = ch*64 + lane;
        float4 p0 = pts[j0];
        float4 p1 = pts[j0 + 32];
        float t0 = fmaf(qz2, p0.z, -qw);
        t0 = fmaf(qy2, p0.y, t0);
        t0 = fmaf(qx2, p0.x, t0);
        unsigned e0 = fenc(t0 - p0.w);
        float t1 = fmaf(qz2, p1.z, -qw);
        t1 = fmaf(qy2, p1.y, t1);
        t1 = fmaf(qx2, p1.x, t1);
        unsigned e1 = fenc(t1 - p1.w);

        unsigned mask = __ballot_sync(FULLM, e0 > thr);
        while (mask){
            int src = __ffs(mask) - 1;
            mask &= mask - 1;
            unsigned e = __shfl_sync(FULLM, e0, src);
            if (e > thr){
                unsigned mv = __reduce_min_sync(FULLM, be);
                if (e > mv){
                    unsigned own = __ballot_sync(FULLM, be == mv);
                    int ml = __ffs(own) - 1;
                    if (lane == ml){ be = e; bi = j0 - lane + src; }
                }
                thr = mv;
            }
        }
        mask = __ballot_sync(FULLM, e1 > thr);
        while (mask){
            int src = __ffs(mask) - 1;
            mask &= mask - 1;
            unsigned e = __shfl_sync(FULLM, e1, src);
            if (e > thr){
                unsigned mv = __reduce_min_sync(FULLM, be);
                if (e > mv){
                    unsigned own = __ballot_sync(FULLM, be == mv);
                    int ml = __ffs(own) - 1;
                    if (lane == ml){ be = e; bi = j0 - lane + 32 + src; }
                }
                thr = mv;
            }
        }
    }
    if (lane < KNN)
        g_idx[((size_t)b*NN + i)*KNN + lane] = bi;
}

// ---------------- gemmYT v2: Y' = s*(x@Wlo^T), T' = s*(x@Wd^T)+b -----------
template<int C, int SEL>
__global__ __launch_bounds__(256) void gemmYT_kernel(
    const float* __restrict__ x, const float* __restrict__ W,
    const float* __restrict__ bng, const float* __restrict__ bnb,
    const float* __restrict__ bnm, const float* __restrict__ bnv)
{
    const float* __restrict__ xin = (SEL == 0) ? x : (SEL == 1) ? g_x1 : g_x2;

    __shared__ __align__(16) float Wlo[C*64];
    __shared__ __align__(16) float Wd [C*64];
    __shared__ __align__(16) float xS [32*C];

    int tid = threadIdx.x;
    int pt0 = blockIdx.x*32;

    for (int t = tid; t < C*64; t += 256){
        int o = t & 63, c = t >> 6;
        float lo = W[(size_t)o*(2*C) + c];
        Wlo[c*64 + o] = lo;
        Wd [c*64 + o] = W[(size_t)o*(2*C) + C + c] - lo;
    }
    for (int t = tid; t < 32*C; t += 256){
        int p = t / C, c = t % C;
        xS[p*C + c] = xin[((size_t)pt0 + p)*C + c];
    }
    __syncthreads();

    int o0 = (tid & 15)*4;
    int p0 = (tid >> 4)*2, p1 = p0 + 1;

    float aY0[4]={0,0,0,0}, aT0[4]={0,0,0,0};
    float aY1[4]={0,0,0,0}, aT1[4]={0,0,0,0};

#pragma unroll 4
    for (int c = 0; c < C; c++){
        float4 wl = *(const float4*)&Wlo[c*64 + o0];
        float4 wd = *(const float4*)&Wd [c*64 + o0];
        float x0 = xS[p0*C + c];
        float x1 = xS[p1*C + c];
        aY0[0]=fmaf(x0,wl.x,aY0[0]); aY0[1]=fmaf(x0,wl.y,aY0[1]);
        aY0[2]=fmaf(x0,wl.z,aY0[2]); aY0[3]=fmaf(x0,wl.w,aY0[3]);
        aT0[0]=fmaf(x0,wd.x,aT0[0]); aT0[1]=fmaf(x0,wd.y,aT0[1]);
        aT0[2]=fmaf(x0,wd.z,aT0[2]); aT0[3]=fmaf(x0,wd.w,aT0[3]);
        aY1[0]=fmaf(x1,wl.x,aY1[0]); aY1[1]=fmaf(x1,wl.y,aY1[1]);
        aY1[2]=fmaf(x1,wl.z,aY1[2]); aY1[3]=fmaf(x1,wl.w,aY1[3]);
        aT1[0]=fmaf(x1,wd.x,aT1[0]); aT1[1]=fmaf(x1,wd.y,aT1[1]);
        aT1[2]=fmaf(x1,wd.z,aT1[2]); aT1[3]=fmaf(x1,wd.w,aT1[3]);
    }

    float4 gv = *(const float4*)&bng[o0];
    float4 bv = *(const float4*)&bnb[o0];
    float4 mv = *(const float4*)&bnm[o0];
    float4 vv = *(const float4*)&bnv[o0];
    float s[4], bo[4];
    s[0] = gv.x*rsqrtf(vv.x + EPSB); bo[0] = bv.x - mv.x*s[0];
    s[1] = gv.y*rsqrtf(vv.y + EPSB); bo[1] = bv.y - mv.y*s[1];
    s[2] = gv.z*rsqrtf(vv.z + EPSB); bo[2] = bv.z - mv.z*s[2];
    s[3] = gv.w*rsqrtf(vv.w + EPSB); bo[3] = bv.w - mv.w*s[3];

    float4 r;
    r = make_float4(s[0]*aY0[0], s[1]*aY0[1], s[2]*aY0[2], s[3]*aY0[3]);
    *(float4*)&g_Y[((size_t)pt0 + p0)*64 + o0] = r;
    r = make_float4(s[0]*aY1[0], s[1]*aY1[1], s[2]*aY1[2], s[3]*aY1[3]);
    *(float4*)&g_Y[((size_t)pt0 + p1)*64 + o0] = r;
    r = make_float4(fmaf(s[0],aT0[0],bo[0]), fmaf(s[1],aT0[1],bo[1]),
                    fmaf(s[2],aT0[2],bo[2]), fmaf(s[3],aT0[3],bo[3]));
    *(float4*)&g_T[((size_t)pt0 + p0)*64 + o0] = r;
    r = make_float4(fmaf(s[0],aT1[0],bo[0]), fmaf(s[1],aT1[1],bo[1]),
                    fmaf(s[2],aT1[2],bo[2]), fmaf(s[3],aT1[3],bo[3]));
    *(float4*)&g_T[((size_t)pt0 + p1)*64 + o0] = r;
}

// ---------------- edge_conv2 v2: 256 thr, 5x8 micro-tile; writes g_pts -----
template<int SEL_OUT>
__global__ __launch_bounds__(256) void edge_conv2_kernel(
    const float* __restrict__ Wb,
    const float* __restrict__ bng, const float* __restrict__ bnb,
    const float* __restrict__ bnm, const float* __restrict__ bnv)
{
    float* __restrict__ xout = (SEL_OUT == 1) ? g_x1 : g_x2;

    __shared__ __align__(16) float Ws[64*64];
    __shared__ __align__(16) float As[64*161];
    __shared__ __align__(16) float red[4*8*64];
    __shared__ int idxS[160];

    int tid = threadIdx.x;
    int pt0 = blockIdx.x*8;

    for (int t = tid; t < 4096; t += 256){
        int o = t & 63, c = t >> 6;
        Ws[c*64 + o] = Wb[(size_t)o*64 + c];
    }
    if (tid < 160) idxS[tid] = g_idx[(size_t)pt0*KNN + tid];
    __syncthreads();

    for (int e = tid; e < 160*64; e += 256){
        int r = e >> 6, c = e & 63;
        int p = r / KNN;
        int bb = (pt0 + p) >> 11;
        int j = idxS[r];
        float v = g_Y[((size_t)bb*NN + j)*64 + c] + g_T[((size_t)pt0 + p)*64 + c];
        As[c*161 + r] = lrelu(v);
    }

    int r5 = tid & 31;
    int og = (tid >> 5) * 8;

    float s2[8], b2[8];
#pragma unroll
    for (int q = 0; q < 8; q++){
        int o = og + q;
        float r = rsqrtf(bnv[o] + EPSB);
        s2[q] = bng[o]*r; b2[q] = bnb[o] - bnm[o]*s2[q];
    }
    __syncthreads();

    float acc[5][8];
#pragma unroll
    for (int i = 0; i < 5; i++)
#pragma unroll
        for (int q = 0; q < 8; q++) acc[i][q] = 0.f;

#pragma unroll 4
    for (int c = 0; c < 64; c++){
        float4 wA = *(const float4*)&Ws[c*64 + og];
        float4 wB = *(const float4*)&Ws[c*64 + og + 4];
        float a[5];
#pragma unroll
        for (int i = 0; i < 5; i++) a[i] = As[c*161 + r5*5 + i];
#pragma unroll
        for (int i = 0; i < 5; i++){
            acc[i][0]=fmaf(a[i],wA.x,acc[i][0]); acc[i][1]=fmaf(a[i],wA.y,acc[i][1]);
            acc[i][2]=fmaf(a[i],wA.z,acc[i][2]); acc[i][3]=fmaf(a[i],wA.w,acc[i][3]);
            acc[i][4]=fmaf(a[i],wB.x,acc[i][4]); acc[i][5]=fmaf(a[i],wB.y,acc[i][5]);
            acc[i][6]=fmaf(a[i],wB.z,acc[i][6]); acc[i][7]=fmaf(a[i],wB.w,acc[i][7]);
        }
    }

    int p    = r5 >> 2;
    int part = r5 & 3;
#pragma unroll
    for (int q = 0; q < 8; q++){
        float mx = -CUDART_INF_F;
#pragma unroll
        for (int i = 0; i < 5; i++)
            mx = fmaxf(mx, lrelu(fmaf(acc[i][q], s2[q], b2[q])));
        red[(part*8 + p)*64 + og + q] = mx;
    }
    __syncthreads();

    for (int t = tid; t < 512; t += 256){
        int pp = t >> 6, oo = t & 63;
        float m = red[(0*8 + pp)*64 + oo];
        m = fmaxf(m, red[(1*8 + pp)*64 + oo]);
        m = fmaxf(m, red[(2*8 + pp)*64 + oo]);
        m = fmaxf(m, red[(3*8 + pp)*64 + oo]);
        xout[((size_t)pt0 + pp)*64 + oo] = m;
    }

    // fused prep for the NEXT stage's kNN: pts = (c6,c7,c8,|p|^2) from red[]
    if (tid < 8){
        int pp = tid;
        float v[3];
#pragma unroll
        for (int c = 0; c < 3; c++){
            float m = red[(0*8 + pp)*64 + 6 + c];
            m = fmaxf(m, red[(1*8 + pp)*64 + 6 + c]);
            m = fmaxf(m, red[(2*8 + pp)*64 + 6 + c]);
            m = fmaxf(m, red[(3*8 + pp)*64 + 6 + c]);
            v[c] = m;
        }
        g_pts[pt0 + pp] = make_float4(v[0], v[1], v[2],
                                      v[0]*v[0] + v[1]*v[1] + v[2]*v[2]);
    }
}

// ---------------- edge_max (stage 3): x3 = max_k lrelu(Y'[j]+T'[i]) --------
__global__ __launch_bounds__(256) void edge_max_kernel()
{
    __shared__ int idxS[4*KNN];
    int tid = threadIdx.x;
    int pt0 = blockIdx.x*4;
    if (tid < 4*KNN) idxS[tid] = g_idx[(size_t)pt0*KNN + tid];
    __syncthreads();

    int p = tid >> 6, o = tid & 63;
    int pt = pt0 + p;
    int bb = pt >> 11;
    float tv = g_T[(size_t)pt*64 + o];
    float m = -CUDART_INF_F;
#pragma unroll
    for (int k = 0; k < KNN; k++){
        int j = idxS[p*KNN + k];
        m = fmaxf(m, lrelu(g_Y[((size_t)bb*NN + j)*64 + o] + tv));
    }
    g_x3[(size_t)pt*64 + o] = m;
}

// ---------------- init / final GEMM v2 / outputs ---------------------------
__global__ void init_gmax_kernel(){
    int t = blockIdx.x*256 + threadIdx.x;
    if (t < BB*1024) g_gmax[t] = 0u;
}

__global__ __launch_bounds__(256) void final_kernel(
    const float* __restrict__ W6,
    const float* __restrict__ bn6g, const float* __restrict__ bn6b,
    const float* __restrict__ bn6m, const float* __restrict__ bn6v)
{
    extern __shared__ float dsm[];
    float* Bs = dsm;              // [192*68]
    float* As = dsm + 192*68;     // [192*68]
    __shared__ float ss6[64], sb6[64];
    __shared__ float red[64*16];

    int tid = threadIdx.x;
    int n0 = blockIdx.x*64;
    int bb = blockIdx.y;
    int mc = blockIdx.z;

    if (tid < 64){
        int o = n0 + tid;
        float r = rsqrtf(bn6v[o] + EPSB);
        ss6[tid] = bn6g[o]*r; sb6[tid] = bn6b[o] - bn6m[o]*ss6[tid];
    }

    for (int ch = 0; ch < 3; ch++)
        for (int t = tid; t < 4096; t += 256){
            int nn = t >> 6, c = t & 63;
            Bs[(ch*64 + c)*68 + nn] = W6[(size_t)(n0+nn)*192 + ch*64 + c];
        }
    __syncthreads();

    int tm = tid & 15, tn = tid >> 4;
    float s6[4], b6[4];
#pragma unroll
    for (int q = 0; q < 4; q++){ s6[q] = ss6[tn*4+q]; b6[q] = sb6[tn*4+q]; }

    float vmax[4] = {-CUDART_INF_F, -CUDART_INF_F, -CUDART_INF_F, -CUDART_INF_F};

    for (int mi = mc*8; mi < mc*8 + 8; mi++){
        size_t m1 = (size_t)bb*NN + mi*64;
        __syncthreads();
        {
            for (int t = tid; t < 4096; t += 256){
                int m = t >> 6, c = t & 63;
                As[(0*64 + c)*68 + m] = g_x1[(m1 + m)*64 + c];
            }
            for (int t = tid; t < 4096; t += 256){
                int m = t >> 6, c = t & 63;
                As[(1*64 + c)*68 + m] = g_x2[(m1 + m)*64 + c];
            }
            for (int t = tid; t < 4096; t += 256){
                int m = t >> 6, c = t & 63;
                As[(2*64 + c)*68 + m] = g_x3[(m1 + m)*64 + c];
            }
        }
        __syncthreads();

        float acc[4][4];
#pragma unroll
        for (int i = 0; i < 4; i++)
#pragma unroll
            for (int j = 0; j < 4; j++) acc[i][j] = 0.f;

#pragma unroll 8
        for (int c = 0; c < 192; c++){
            float4 a  = *(const float4*)&As[c*68 + tm*4];
            float4 bv = *(const float4*)&Bs[c*68 + tn*4];
            acc[0][0] = fmaf(a.x,bv.x,acc[0][0]); acc[0][1] = fmaf(a.x,bv.y,acc[0][1]);
            acc[0][2] = fmaf(a.x,bv.z,acc[0][2]); acc[0][3] = fmaf(a.x,bv.w,acc[0][3]);
            acc[1][0] = fmaf(a.y,bv.x,acc[1][0]); acc[1][1] = fmaf(a.y,bv.y,acc[1][1]);
            acc[1][2] = fmaf(a.y,bv.z,acc[1][2]); acc[1][3] = fmaf(a.y,bv.w,acc[1][3]);
            acc[2][0] = fmaf(a.z,bv.x,acc[2][0]); acc[2][1] = fmaf(a.z,bv.y,acc[2][1]);
            acc[2][2] = fmaf(a.z,bv.z,acc[2][2]); acc[2][3] = fmaf(a.z,bv.w,acc[2][3]);
            acc[3][0] = fmaf(a.w,bv.x,acc[3][0]); acc[3][1] = fmaf(a.w,bv.y,acc[3][1]);
            acc[3][2] = fmaf(a.w,bv.z,acc[3][2]); acc[3][3] = fmaf(a.w,bv.w,acc[3][3]);
        }
#pragma unroll
        for (int nq = 0; nq < 4; nq++)
#pragma unroll
            for (int mq = 0; mq < 4; mq++)
                vmax[nq] = fmaxf(vmax[nq], lrelu(fmaf(acc[mq][nq], s6[nq], b6[nq])));
    }

    __syncthreads();
#pragma unroll
    for (int nq = 0; nq < 4; nq++) red[(tn*4+nq)*16 + tm] = vmax[nq];
    __syncthreads();
    if (tid < 64){
        float mx = -CUDART_INF_F;
#pragma unroll
        for (int t = 0; t < 16; t++) mx = fmaxf(mx, red[tid*16 + t]);
        atomicMax(&g_gmax[bb*1024 + n0 + tid], fencs(mx));
    }
}

__global__ void feat_kernel(float* __restrict__ out){
    int t = blockIdx.x*256 + threadIdx.x;
    if (t < BB*1024) out[t] = fdec(g_gmax[t]);
}

// ---------------- x4^T via smem transpose ----------------------------------
__global__ __launch_bounds__(256) void x4t_kernel(float* __restrict__ out)
{
    __shared__ float T[64*65];
    int tid = threadIdx.x;
    int n0 = blockIdx.x*64;
    int bb = blockIdx.y;
    int ch = blockIdx.z;
    const float* src = (ch == 0) ? g_x1 : (ch == 1) ? g_x2 : g_x3;

    for (int t = tid; t < 4096; t += 256){
        int c = t & 63, n = t >> 6;
        T[c*65 + n] = src[((size_t)bb*NN + n0 + n)*64 + c];
    }
    __syncthreads();
    size_t base = (size_t)BB*1024 + (size_t)bb*192*NN + (size_t)ch*64*NN;
    for (int t = tid; t < 4096; t += 256){
        int n = t & 63, c = t >> 6;
        out[base + (size_t)c*NN + n0 + n] = T[c*65 + n];
    }
}

// ---------------- launch: fork-join across two streams ---------------------
extern "C" void kernel_launch(void* const* d_in, const int* in_sizes, int n_in,
                              void* d_out, int out_size)
{
    const float* x    = (const float*)d_in[0];
    const float* W1   = (const float*)d_in[1];
    const float* W2   = (const float*)d_in[2];
    const float* W3   = (const float*)d_in[3];
    const float* W4   = (const float*)d_in[4];
    const float* W5   = (const float*)d_in[5];
    const float* W6   = (const float*)d_in[6];
    const float* bng  = (const float*)d_in[7];
    const float* bnb  = (const float*)d_in[8];
    const float* bnm  = (const float*)d_in[9];
    const float* bnv  = (const float*)d_in[10];
    const float* bn6g = (const float*)d_in[11];
    const float* bn6b = (const float*)d_in[12];
    const float* bn6m = (const float*)d_in[13];
    const float* bn6v = (const float*)d_in[14];
    float* out = (float*)d_out;

    static cudaStream_t s1 = nullptr;
    static cudaEvent_t evF, evB, evX1, evC, evX2, evE, evM, evJ;
    if (!s1){
        cudaStreamCreateWithFlags(&s1, cudaStreamNonBlocking);
        cudaEventCreateWithFlags(&evF,  cudaEventDisableTiming);
        cudaEventCreateWithFlags(&evB,  cudaEventDisableTiming);
        cudaEventCreateWithFlags(&evX1, cudaEventDisableTiming);
        cudaEventCreateWithFlags(&evC,  cudaEventDisableTiming);
        cudaEventCreateWithFlags(&evX2, cudaEventDisableTiming);
        cudaEventCreateWithFlags(&evE,  cudaEventDisableTiming);
        cudaEventCreateWithFlags(&evM,  cudaEventDisableTiming);
        cudaEventCreateWithFlags(&evJ,  cudaEventDisableTiming);
        cudaFuncSetAttribute(final_kernel,
            cudaFuncAttributeMaxDynamicSharedMemorySize, 2*192*68*4);
    }
    const int FSMEM = 2*192*68*4;

    // ---- Stage 1 ----                               (kernel launch order)
    prep_pts_kernel<<<NTOT/256, 256>>>(x);                              // 0
    cudaEventRecord(evF, 0);
    cudaStreamWaitEvent(s1, evF, 0);
    gemmYT_kernel<3,0><<<NTOT/32, 256, 0, s1>>>(x, W1, bng, bnb, bnm, bnv); // 1
    cudaEventRecord(evB, s1);
    knn_kernel<<<dim3(BB, NN/8), 256>>>();                              // 2
    cudaStreamWaitEvent(0, evB, 0);
    edge_conv2_kernel<1><<<NTOT/8, 256>>>(W2, bng+64, bnb+64, bnm+64, bnv+64); // 3 <- ncu
    cudaEventRecord(evX1, 0);
    init_gmax_kernel<<<32, 256>>>();                                    // 4 (s0)

    // ---- Stage 2 ----  gemmYT on s1 overlaps knn on s0
    cudaStreamWaitEvent(s1, evX1, 0);
    gemmYT_kernel<64,1><<<NTOT/32, 256, 0, s1>>>(x, W3, bng+2*64, bnb+2*64, bnm+2*64, bnv+2*64);
    cudaEventRecord(evC, s1);
    knn_kernel<<<dim3(BB, NN/8), 256>>>();
    cudaStreamWaitEvent(0, evC, 0);
    edge_conv2_kernel<2><<<NTOT/8, 256>>>(W4, bng+3*64, bnb+3*64, bnm+3*64, bnv+3*64);
    cudaEventRecord(evX2, 0);

    // ---- Stage 3 ----
    cudaStreamWaitEvent(s1, evX2, 0);
    gemmYT_kernel<64,2><<<NTOT/32, 256, 0, s1>>>(x, W5, bng+4*64, bnb+4*64, bnm+4*64, bnv+4*64);
    cudaEventRecord(evE, s1);
    knn_kernel<<<dim3(BB, NN/8), 256>>>();
    cudaStreamWaitEvent(0, evE, 0);
    edge_max_kernel<<<NTOT/4, 256>>>();
    cudaEventRecord(evM, 0);

    // ---- Final: x4t (s1) overlaps final GEMM (s0) ----
    cudaStreamWaitEvent(s1, evM, 0);
    x4t_kernel<<<dim3(NN/64, BB, 3), 256, 0, s1>>>(out);
    cudaEventRecord(evJ, s1);
    final_kernel<<<dim3(1024/64, BB, 4), 256, FSMEM>>>(W6, bn6g, bn6b, bn6m, bn6v);
    feat_kernel<<<32, 256>>>(out);
    cudaStreamWaitEvent(0, evJ, 0);   // join s1 into s0 before capture ends
}